// round 13
// baseline (speedup 1.0000x reference)
#include <cuda_runtime.h>
#include <cuda_fp16.h>
#include <math_constants.h>

#define B_   16
#define N_   4096
#define NP_  1024
#define NS_  32
#define NROWS 524288   // B_*NP_*NS_

typedef unsigned long long ull;

// ------------------------- static device scratch (no allocation) -------------------------
__device__ __align__(16) float g_newxyz[B_*NP_*3];
__device__ __align__(16) float4 g_xyzw[B_*N_];       // (x,y,z,sq)
__device__ int   g_knn[B_*NP_*NS_];
__device__ __align__(16) float g_P [4194304];        // 65536 x 64   pts @ W0[3:]
__device__ __align__(16) unsigned g_Y1h[16777216];   // fp16: blocked 4096 x 8 x 128 x uint4
__device__ __align__(16) unsigned g_Y2h[16777216];   // fp16: blocked 4096 x 8 x 128 x uint4
__device__ __align__(16) float g_Mx[B_*NP_*128];     // raw per-(query,ch) max of layer-3 out
__device__ __align__(16) float g_Mn[B_*NP_*128];     // raw per-(query,ch) min
__device__ float g_psum[4096*128];
__device__ float g_psq [4096*128];
__device__ float g_scale[3][128];
__device__ float g_shift[3][128];
__device__ __align__(16) float g_wt0[67*64];
__device__ __align__(16) float g_wt1[64*64];
__device__ __align__(16) float g_wt2[64*128];

// ------------------------- packed helpers -------------------------
__device__ __forceinline__ void fma2(ull& d, ull a, ull b) {
    asm("fma.rn.f32x2 %0, %1, %2, %0;" : "+l"(d) : "l"(a), "l"(b));
}
__device__ __forceinline__ ull pk2(float x) {
    ull u;
    asm("mov.b64 %0, {%1, %2};" : "=l"(u) : "f"(x), "f"(x));
    return u;
}
__device__ __forceinline__ float2 up2(ull u) {
    float2 f;
    asm("mov.b64 {%0, %1}, %2;" : "=f"(f.x), "=f"(f.y) : "l"(u));
    return f;
}
__device__ __forceinline__ unsigned packh2(float a, float b) {
    __half2 h = __float22half2_rn(make_float2(a, b));
    return *reinterpret_cast<unsigned*>(&h);
}
__device__ __forceinline__ unsigned packh2u(ull u) {
    float2 f = up2(u);
    return packh2(f.x, f.y);
}
__device__ __forceinline__ float2 unph2(unsigned u) {
    return __half22float2(*reinterpret_cast<const __half2*>(&u));
}

// ------------------------- init: transpose weights to [K][OC] -------------------------
__global__ void k_init(const float* __restrict__ w0, const float* __restrict__ w1,
                       const float* __restrict__ w2) {
    int t = blockIdx.x * blockDim.x + threadIdx.x;
    int stride = gridDim.x * blockDim.x;
    for (int l = t; l < 64*67; l += stride) { int oc = l / 67, k = l - oc*67; g_wt0[k*64 + oc] = w0[l]; }
    for (int l = t; l < 64*64; l += stride) { int oc = l >> 6, k = l & 63;    g_wt1[k*64 + oc] = w1[l]; }
    for (int l = t; l < 128*64; l += stride){ int oc = l >> 6, k = l & 63;    g_wt2[k*128 + oc] = w2[l]; }
}

// ------------------------- fused front: P precompute | xyzw table | FPS -------------------
__global__ __launch_bounds__(1024)
void k_front(const float* __restrict__ xyz, const float* __restrict__ pts,
             float* __restrict__ out) {
    __shared__ __align__(16) float ws[4096];
    __shared__ unsigned sv[2][32]; __shared__ int si_[2][32];
    int blk = blockIdx.x, t = threadIdx.x;

    if (blk < 128) {
        // ---- P = pts @ W0[3:,:]
        for (int i = t; i < 4096; i += 1024) ws[i] = g_wt0[192 + i];
        __syncthreads();
        int row  = blk * 512 + (t >> 1);
        int half = (t & 1) * 32;
        const float4* xr = (const float4*)(pts + (size_t)row * 64);
        ull acc2[16];
#pragma unroll
        for (int p = 0; p < 16; p++) acc2[p] = 0ull;
        float4 a0 = __ldg(&xr[0]);
        float4 a1 = __ldg(&xr[1]);
#pragma unroll 1
        for (int kc = 0; kc < 16; kc++) {
            float4 xv = a0; a0 = a1;
            a1 = __ldg(&xr[(kc < 14) ? (kc + 2) : 15]);
            float xs[4] = {xv.x, xv.y, xv.z, xv.w};
#pragma unroll
            for (int kk = 0; kk < 4; kk++) {
                ull xk2 = pk2(xs[kk]);
                const ulonglong2* wr = (const ulonglong2*)(ws + (kc*4 + kk)*64 + half);
#pragma unroll
                for (int p = 0; p < 8; p++) {
                    ulonglong2 wv = wr[p];
                    fma2(acc2[p*2],   xk2, wv.x);
                    fma2(acc2[p*2+1], xk2, wv.y);
                }
            }
        }
        ulonglong2* po = (ulonglong2*)(g_P + (size_t)row * 64 + half);
#pragma unroll
        for (int p = 0; p < 8; p++) po[p] = make_ulonglong2(acc2[2*p], acc2[2*p+1]);
        return;
    }
    if (blk < 192) {
        int n = (blk - 128) * 1024 + t;
        const float* X = xyz + (size_t)n * 3;
        float x = X[0], y = X[1], z = X[2];
        float sq = __fadd_rn(__fadd_rn(__fmul_rn(x,x), __fmul_rn(y,y)), __fmul_rn(z,z));
        g_xyzw[n] = make_float4(x, y, z, sq);
        return;
    }

    // ---- FPS: single barrier per iteration (double-buffered winner slots)
    int b = blk - 192;
    int lane = t & 31, w = t >> 5;
    const float* X = xyz + (size_t)b * N_ * 3;
    float px[4], py[4], pz[4], dd[4];
#pragma unroll
    for (int j = 0; j < 4; j++) {
        int n = t*4 + j;
        px[j] = X[n*3]; py[j] = X[n*3+1]; pz[j] = X[n*3+2];
        dd[j] = 1e10f;
    }
    float ccx = X[0], ccy = X[1], ccz = X[2];
    float* nx = g_newxyz + (size_t)b * NP_ * 3;
    float* ox = out + (size_t)b * NP_ * 3;

    for (int i = 0; i < NP_; i++) {
        if (t == 0) {
            nx[i*3] = ccx; nx[i*3+1] = ccy; nx[i*3+2] = ccz;
            ox[i*3] = ccx; ox[i*3+1] = ccy; ox[i*3+2] = ccz;
        }
        float bv = -1.0f; int bi = 0;
#pragma unroll
        for (int j = 0; j < 4; j++) {
            float dx = __fsub_rn(px[j], ccx);
            float dy = __fsub_rn(py[j], ccy);
            float dz = __fsub_rn(pz[j], ccz);
            float d  = __fadd_rn(__fadd_rn(__fmul_rn(dx,dx), __fmul_rn(dy,dy)), __fmul_rn(dz,dz));
            dd[j] = fminf(dd[j], d);
            if (dd[j] > bv) { bv = dd[j]; bi = t*4 + j; }
        }
        unsigned kv   = __float_as_uint(bv);
        unsigned vmax = __reduce_max_sync(0xffffffffu, kv);
        unsigned cand = (kv == vmax) ? (unsigned)bi : 0xffffffffu;
        unsigned imin = __reduce_min_sync(0xffffffffu, cand);
        int p = i & 1;
        if (lane == 0) { sv[p][w] = vmax; si_[p][w] = (int)imin; }
        __syncthreads();
        unsigned kv2 = sv[p][lane];
        int      ii  = si_[p][lane];
        unsigned vm2 = __reduce_max_sync(0xffffffffu, kv2);
        unsigned c2  = (kv2 == vm2) ? (unsigned)ii : 0xffffffffu;
        unsigned win = __reduce_min_sync(0xffffffffu, c2);
        const float* Pp = X + (size_t)win * 3;
        ccx = Pp[0]; ccy = Pp[1]; ccz = Pp[2];
    }
}

__device__ __forceinline__ unsigned fkey(float v) {
    unsigned u = __float_as_uint(v);
    return u ^ (unsigned)(((int)u >> 31) | 0x80000000);
}

// ------------------------- kNN: histogram radix-select (one block / query) -----------------
__global__ __launch_bounds__(128)
void k_knn() {
    int q = blockIdx.x, b = q >> 10, t = threadIdx.x;
    int lane = t & 31, w = t >> 5;
    const float4* X4 = g_xyzw + (size_t)b * N_;
    const float* Q = g_newxyz + (size_t)q * 3;
    float qx = Q[0], qy = Q[1], qz = Q[2];
    float sqn = __fadd_rn(__fadd_rn(__fmul_rn(qx,qx), __fmul_rn(qy,qy)), __fmul_rn(qz,qz));

    unsigned key[32];
#pragma unroll
    for (int i = 0; i < 32; i++) {
        float4 v = __ldg(&X4[i*128 + t]);
        float dot = __fadd_rn(__fadd_rn(__fmul_rn(qx,v.x), __fmul_rn(qy,v.y)), __fmul_rn(qz,v.z));
        float d2  = __fsub_rn(__fadd_rn(sqn, v.w), __fmul_rn(2.0f, dot));
        key[i] = fkey(d2);
    }

    __shared__ unsigned hist[2048];
    __shared__ unsigned sw[4];
    __shared__ unsigned spiv[3];
    __shared__ unsigned candk[64];
    __shared__ int candi[64];
    __shared__ int candn;

    for (int j = t; j < 2048; j += 128) hist[j] = 0;
    if (t == 0) candn = 0;
    __syncthreads();
#pragma unroll
    for (int i = 0; i < 32; i++) atomicAdd(&hist[key[i] >> 21], 1u);
    __syncthreads();
    unsigned s = 0;
#pragma unroll
    for (int j = 0; j < 16; j++) s += hist[t*16 + j];
    unsigned inc = s;
#pragma unroll
    for (int o = 1; o < 32; o <<= 1) { unsigned nn = __shfl_up_sync(~0u, inc, o); if (lane >= o) inc += nn; }
    if (lane == 31) sw[w] = inc;
    __syncthreads();
    unsigned wbase = 0;
    for (int j = 0; j < w; j++) wbase += sw[j];
    unsigned base = wbase + inc - s;
    if (base < 32 && base + s >= 32) {
        unsigned cum = base;
#pragma unroll
        for (int j = 0; j < 16; j++) {
            unsigned c = hist[t*16 + j];
            if (cum + c >= 32) { spiv[0] = t*16 + j; spiv[1] = cum; spiv[2] = c; break; }
            cum += c;
        }
    }
    __syncthreads();
    unsigned pb1 = spiv[0];
    unsigned cb  = spiv[1];
    unsigned pc  = spiv[2];
    unsigned Kstar, width;

    if (pc > 64) {
        unsigned need2 = 32 - cb;
        for (int j = t; j < 2048; j += 128) hist[j] = 0;
        __syncthreads();
#pragma unroll
        for (int i = 0; i < 32; i++)
            if ((key[i] >> 21) == pb1) atomicAdd(&hist[(key[i] >> 10) & 2047], 1u);
        __syncthreads();
        s = 0;
#pragma unroll
        for (int j = 0; j < 16; j++) s += hist[t*16 + j];
        inc = s;
#pragma unroll
        for (int o = 1; o < 32; o <<= 1) { unsigned nn = __shfl_up_sync(~0u, inc, o); if (lane >= o) inc += nn; }
        if (lane == 31) sw[w] = inc;
        __syncthreads();
        wbase = 0;
        for (int j = 0; j < w; j++) wbase += sw[j];
        base = wbase + inc - s;
        if (base < need2 && base + s >= need2) {
            unsigned cum = base;
#pragma unroll
            for (int j = 0; j < 16; j++) {
                unsigned c = hist[t*16 + j];
                if (cum + c >= need2) { spiv[0] = t*16 + j; spiv[1] = cum; break; }
                cum += c;
            }
        }
        __syncthreads();
        Kstar = (pb1 << 21) | (spiv[0] << 10);
        width = 1u << 10;
        cb = cb + spiv[1];
        __syncthreads();
    } else {
        Kstar = pb1 << 21;
        width = 1u << 21;
    }

    int ct = 0;
#pragma unroll
    for (int i = 0; i < 32; i++) ct += (key[i] < Kstar);
    int inci = ct;
#pragma unroll
    for (int o = 1; o < 32; o <<= 1) { int nn = __shfl_up_sync(~0u, inci, o); if (lane >= o) inci += nn; }
    if (lane == 31) sw[w] = (unsigned)inci;
    __syncthreads();
    int wb = 0;
    for (int j = 0; j < w; j++) wb += (int)sw[j];
    int slot = wb + inci - ct;
    int* KO = g_knn + (size_t)q * NS_;
#pragma unroll
    for (int i = 0; i < 32; i++) {
        unsigned k = key[i];
        if (k < Kstar) { KO[slot++] = i*128 + t; }
        else if (k - Kstar < width) {
            int p = atomicAdd(&candn, 1);
            if (p < 64) { candk[p] = k; candi[p] = i*128 + t; }
        }
    }
    __syncthreads();
    int L = candn; if (L > 64) L = 64;
    int need = 32 - (int)cb;
    if (t < L) {
        unsigned mk = candk[t]; int mi = candi[t];
        int rank = 0;
        for (int j = 0; j < L; j++) {
            unsigned kj = candk[j];
            rank += (kj < mk) || (kj == mk && candi[j] < mi);
        }
        if (rank < need) KO[cb + rank] = mi;
    }
}

// ---------- layer 1: gather(P) + rel_xyz @ W0[:3], half-row per thread (256 thr) -----------
__global__ __launch_bounds__(256)
void k_gemm1(const float* __restrict__ xyz) {
    __shared__ float ws[192];
    __shared__ float tile[64*65];
    __shared__ float ps[256], pq[256];
    int t = threadIdx.x;
    int row = t & 127, half = t >> 7;
    for (int i = t; i < 192; i += 256) ws[i] = g_wt0[i];
    __syncthreads();

    size_t r = (size_t)blockIdx.x * 128 + row;
    int b  = (int)(r >> 15);
    int bm = (int)(r >> 5);
    int j  = g_knn[r];
    const float* Pt = xyz + ((size_t)b * N_ + j) * 3;
    const float* Q  = g_newxyz + (size_t)bm * 3;
    float f0 = Pt[0] - Q[0], f1 = Pt[1] - Q[1], f2 = Pt[2] - Q[2];

    const float4* prow = (const float4*)(g_P + ((size_t)b * N_ + j) * 64) + half*8;
    float4 pv[8];
#pragma unroll
    for (int kc = 0; kc < 8; kc++) pv[kc] = __ldg(&prow[kc]);   // 8 outstanding

    float acc[32];
#pragma unroll
    for (int kc = 0; kc < 8; kc++) {
        int o = half*32 + kc*4;
        acc[kc*4]   = fmaf(f2, ws[128+o],   fmaf(f1, ws[64+o],   fmaf(f0, ws[o],   pv[kc].x)));
        acc[kc*4+1] = fmaf(f2, ws[128+o+1], fmaf(f1, ws[64+o+1], fmaf(f0, ws[o+1], pv[kc].y)));
        acc[kc*4+2] = fmaf(f2, ws[128+o+2], fmaf(f1, ws[64+o+2], fmaf(f0, ws[o+2], pv[kc].z)));
        acc[kc*4+3] = fmaf(f2, ws[128+o+3], fmaf(f1, ws[64+o+3], fmaf(f0, ws[o+3], pv[kc].w)));
    }
    // store fp16 chunks (8 halves per chunk; this thread owns chunks half*4 .. half*4+3)
    uint4* yo = (uint4*)g_Y1h + (size_t)blockIdx.x * 1024 + row;
#pragma unroll
    for (int kc2 = 0; kc2 < 4; kc2++) {
        uint4 v;
        v.x = packh2(acc[kc2*8],   acc[kc2*8+1]);
        v.y = packh2(acc[kc2*8+2], acc[kc2*8+3]);
        v.z = packh2(acc[kc2*8+4], acc[kc2*8+5]);
        v.w = packh2(acc[kc2*8+6], acc[kc2*8+7]);
        yo[(half*4 + kc2)*128] = v;
    }

    // two-phase epilogue (64-row tile) from fp32 accumulators
    float psa = 0.f, pqa = 0.f;
#pragma unroll
    for (int ph = 0; ph < 2; ph++) {
        if ((row >> 6) == ph) {
#pragma unroll
            for (int o = 0; o < 32; o++) tile[(row & 63)*65 + half*32 + o] = acc[o];
        }
        __syncthreads();
        int c = t & 63, g = t >> 6;
#pragma unroll 4
        for (int rr = g*16; rr < g*16 + 16; rr++) {
            float v = tile[rr*65 + c];
            psa += v; pqa = fmaf(v, v, pqa);
        }
        __syncthreads();
    }
    ps[t] = psa; pq[t] = pqa;
    __syncthreads();
    if (t < 64) {
        g_psum[(size_t)blockIdx.x*64 + t] = ps[t] + ps[64+t] + ps[128+t] + ps[192+t];
        g_psq [(size_t)blockIdx.x*64 + t] = pq[t] + pq[64+t] + pq[128+t] + pq[192+t];
    }
}

// ------------------- layer 2: BN0+ReLU(Y1h) @ W1 (f32x2, fp16 in/out, 128 thr) ------------
__global__ __launch_bounds__(128)
void k_gemm2() {
    extern __shared__ __align__(16) float dyn[];
    float* ws   = dyn;            // union with tile
    float* tile = dyn;            // 8320 (used after sync)
    float* sc   = dyn + 8320;     // 64
    float* sh   = sc + 64;        // 64
    float* ps   = sh + 64;        // 128
    float* pq   = ps + 128;       // 128   total 8704 floats
    int t = threadIdx.x;
    for (int i = t; i < 4096; i += 128) ws[i] = g_wt1[i];
    if (t < 64) { sc[t] = g_scale[0][t]; sh[t] = g_shift[0][t]; }
    __syncthreads();

    const uint4* xh = (const uint4*)g_Y1h + (size_t)blockIdx.x * 1024 + t;
    ull acc2[32];
#pragma unroll
    for (int p = 0; p < 32; p++) acc2[p] = 0ull;

    uint4 a0 = xh[0];
    uint4 a1 = xh[128];
#pragma unroll 1
    for (int kc = 0; kc < 8; kc++) {
        uint4 hv = a0; a0 = a1;
        a1 = xh[((kc < 6) ? (kc + 2) : 7) * 128];
        float2 y0 = unph2(hv.x), y1 = unph2(hv.y), y2 = unph2(hv.z), y3 = unph2(hv.w);
        float ys[8] = {y0.x, y0.y, y1.x, y1.y, y2.x, y2.y, y3.x, y3.y};
        int kb = kc * 8;
#pragma unroll
        for (int kk = 0; kk < 8; kk++) {
            float xk = fmaxf(fmaf(ys[kk], sc[kb+kk], sh[kb+kk]), 0.f);
            ull xk2 = pk2(xk);
            const ulonglong2* wr = (const ulonglong2*)(ws + (kb+kk)*64);
#pragma unroll
            for (int p = 0; p < 16; p++) {
                ulonglong2 wv = wr[p];
                fma2(acc2[2*p],   xk2, wv.x);
                fma2(acc2[2*p+1], xk2, wv.y);
            }
        }
    }
    // store Y2 fp16 (8 chunks of 8 halves)
    uint4* yo = (uint4*)g_Y2h + (size_t)blockIdx.x * 1024 + t;
#pragma unroll
    for (int c = 0; c < 8; c++) {
        uint4 v;
        v.x = packh2u(acc2[4*c]);
        v.y = packh2u(acc2[4*c+1]);
        v.z = packh2u(acc2[4*c+2]);
        v.w = packh2u(acc2[4*c+3]);
        yo[c*128] = v;
    }

    __syncthreads();
#pragma unroll
    for (int p = 0; p < 32; p++) {
        float2 f = up2(acc2[p]);
        tile[t*65 + 2*p]     = f.x;
        tile[t*65 + 2*p + 1] = f.y;
    }
    __syncthreads();
    int c = t & 63, g = t >> 6;
    float sa = 0.f, qa = 0.f;
#pragma unroll 4
    for (int rr = g*64; rr < g*64 + 64; rr++) {
        float v = tile[rr*65 + c];
        sa += v; qa = fmaf(v, v, qa);
    }
    ps[g*64 + c] = sa; pq[g*64 + c] = qa;
    __syncthreads();
    if (t < 64) {
        g_psum[(size_t)blockIdx.x*64 + t] = ps[t] + ps[64 + t];
        g_psq [(size_t)blockIdx.x*64 + t] = pq[t] + pq[64 + t];
    }
}

// ------- layer 3: BN1+ReLU(Y2h) @ W2 -> 128 ch; NO Y3 store, per-query raw min/max ---------
__global__ __launch_bounds__(256)
void k_gemm3() {
    extern __shared__ __align__(16) float dyn[];
    float* ws   = dyn;             // union with tile
    float* tile = dyn;             // 16512
    float* sc   = dyn + 16512;     // 64
    float* sh   = sc + 64;         // 64
    float* ps   = sh + 64;         // 256
    float* pq   = ps + 256;        // 256   total 17152 floats
    int t = threadIdx.x;
    for (int i = t; i < 64*128; i += 256) ws[i] = g_wt2[i];
    if (t < 64) { sc[t] = g_scale[1][t]; sh[t] = g_shift[1][t]; }
    __syncthreads();

    int row  = t & 127;
    int half = (t >> 7) * 64;
    const uint4* xh = (const uint4*)g_Y2h + (size_t)blockIdx.x * 1024 + row;
    ull acc2[32];
#pragma unroll
    for (int p = 0; p < 32; p++) acc2[p] = 0ull;

    uint4 a0 = xh[0];
    uint4 a1 = xh[128];
#pragma unroll 1
    for (int kc = 0; kc < 8; kc++) {
        uint4 hv = a0; a0 = a1;
        a1 = xh[((kc < 6) ? (kc + 2) : 7) * 128];
        float2 y0 = unph2(hv.x), y1 = unph2(hv.y), y2 = unph2(hv.z), y3 = unph2(hv.w);
        float ys[8] = {y0.x, y0.y, y1.x, y1.y, y2.x, y2.y, y3.x, y3.y};
        int kb = kc * 8;
#pragma unroll
        for (int kk = 0; kk < 8; kk++) {
            float xk = fmaxf(fmaf(ys[kk], sc[kb+kk], sh[kb+kk]), 0.f);
            ull xk2 = pk2(xk);
            const ulonglong2* wr = (const ulonglong2*)(ws + (kb+kk)*128 + half);
#pragma unroll
            for (int p = 0; p < 16; p++) {
                ulonglong2 wv = wr[p];
                fma2(acc2[2*p],   xk2, wv.x);
                fma2(acc2[2*p+1], xk2, wv.y);
            }
        }
    }

    __syncthreads();   // ws done; tile aliases it
#pragma unroll
    for (int p = 0; p < 32; p++) {
        float2 f = up2(acc2[p]);
        tile[row*129 + half + 2*p]     = f.x;
        tile[row*129 + half + 2*p + 1] = f.y;
    }
    __syncthreads();

    // per-channel sums
    int c = t & 127, g = t >> 7;
    float sa = 0.f, qa = 0.f;
#pragma unroll 4
    for (int rr = g*64; rr < g*64 + 64; rr++) {
        float v = tile[rr*129 + c];
        sa += v; qa = fmaf(v, v, qa);
    }
    ps[g*128 + c] = sa; pq[g*128 + c] = qa;

    // per-(query, channel) raw min/max over the 32-sample groups (block = 4 queries)
#pragma unroll
    for (int e = t; e < 512; e += 256) {
        int qi = e >> 7, ch = e & 127;
        int r0 = qi * 32;
        float mx = tile[r0*129 + ch], mn = mx;
#pragma unroll 4
        for (int rr = r0 + 1; rr < r0 + 32; rr++) {
            float v = tile[rr*129 + ch];
            mx = fmaxf(mx, v); mn = fminf(mn, v);
        }
        g_Mx[(size_t)blockIdx.x*512 + e] = mx;
        g_Mn[(size_t)blockIdx.x*512 + e] = mn;
    }
    __syncthreads();
    if (t < 128) {
        g_psum[(size_t)blockIdx.x*128 + t] = ps[t] + ps[128 + t];
        g_psq [(size_t)blockIdx.x*128 + t] = pq[t] + pq[128 + t];
    }
}

// ------------------------- finalize BN stats: one block per channel -----------------------
__global__ __launch_bounds__(256)
void k_fin(const float* __restrict__ gma, const float* __restrict__ beta,
           int OC, int layer) {
    int c = blockIdx.x, t = threadIdx.x;
    float s = 0.f, s2 = 0.f;
    for (int i = t; i < 4096; i += 256) {
        s  += g_psum[(size_t)i * OC + c];
        s2 += g_psq [(size_t)i * OC + c];
    }
#pragma unroll
    for (int off = 16; off; off >>= 1) {
        s  += __shfl_down_sync(0xffffffffu, s, off);
        s2 += __shfl_down_sync(0xffffffffu, s2, off);
    }
    __shared__ float a[8], a2[8];
    if ((t & 31) == 0) { a[t>>5] = s; a2[t>>5] = s2; }
    __syncthreads();
    if (t == 0) {
        double S = 0.0, S2 = 0.0;
#pragma unroll
        for (int wb = 0; wb < 8; wb++) { S += (double)a[wb]; S2 += (double)a2[wb]; }
        double inv  = 1.0 / (double)NROWS;
        double mean = S * inv;
        double var  = S2 * inv - mean * mean;
        float scale = (float)((double)gma[c] * rsqrt(var + 1e-5));
        float shift = (float)((double)beta[c] - mean * (double)scale);
        g_scale[layer][c] = scale;
        g_shift[layer][c] = shift;
    }
}

// ---------- pool: BN2 applied to raw min/max (monotone-exact) + transposed write -----------
__global__ __launch_bounds__(128)
void k_pool(float* __restrict__ out) {
    __shared__ float sm[128*33];
    int t = threadIdx.x;
    float sc = g_scale[2][t], sh = g_shift[2][t];
    int q0 = blockIdx.x * 32;
    int b  = q0 >> 10;
    const float* src = (sc > 0.f) ? g_Mx : g_Mn;
#pragma unroll 4
    for (int qi = 0; qi < 32; qi++) {
        float v = src[(size_t)(q0 + qi)*128 + t];
        sm[t*33 + qi] = fmaxf(fmaf(v, sc, sh), 0.f);
    }
    __syncthreads();
    int mloc = t & 31, og = t >> 5;
    int mg = q0 & 1023;
#pragma unroll
    for (int i = 0; i < 32; i++) {
        int oc = og + i*4;
        out[49152 + ((size_t)(b*128 + oc))*1024 + mg + mloc] = sm[oc*33 + mloc];
    }
}

// ------------------------- launch --------------------------------------------------------
extern "C" void kernel_launch(void* const* d_in, const int* in_sizes, int n_in,
                              void* d_out, int out_size) {
    const float* xyz = (const float*)d_in[0];
    const float* pts = (const float*)d_in[1];
    const float* w0  = (const float*)d_in[2];
    const float* g0  = (const float*)d_in[4];
    const float* be0 = (const float*)d_in[5];
    const float* w1  = (const float*)d_in[6];
    const float* g1  = (const float*)d_in[8];
    const float* be1 = (const float*)d_in[9];
    const float* w2  = (const float*)d_in[10];
    const float* g2  = (const float*)d_in[12];
    const float* be2 = (const float*)d_in[13];
    float* out = (float*)d_out;

    const int SMEM2 = 8704 * 4;    // 34816 B
    const int SMEM3 = 17152 * 4;   // 68608 B
    cudaFuncSetAttribute(k_gemm2, cudaFuncAttributeMaxDynamicSharedMemorySize, SMEM2);
    cudaFuncSetAttribute(k_gemm3, cudaFuncAttributeMaxDynamicSharedMemorySize, SMEM3);

    k_init<<<64, 256>>>(w0, w1, w2);
    k_front<<<208, 1024>>>(xyz, pts, out);
    k_knn<<<B_*NP_, 128>>>();

    k_gemm1<<<NROWS/128, 256>>>(xyz);
    k_fin<<<64, 256>>>(g0, be0, 64, 0);

    k_gemm2<<<NROWS/128, 128, SMEM2>>>();
    k_fin<<<64, 256>>>(g1, be1, 64, 1);

    k_gemm3<<<NROWS/128, 256, SMEM3>>>();
    k_fin<<<128, 256>>>(g2, be2, 128, 2);

    k_pool<<<B_*NP_/32, 128>>>(out);
}

// round 14
// speedup vs baseline: 1.0052x; 1.0052x over previous
#include <cuda_runtime.h>
#include <math_constants.h>

#define B_   16
#define N_   4096
#define NP_  1024
#define NS_  32
#define NROWS 524288   // B_*NP_*NS_

typedef unsigned long long ull;

// ------------------------- static device scratch (no allocation) -------------------------
__device__ __align__(16) float g_newxyz[B_*NP_*3];
__device__ __align__(16) float4 g_xyzw[B_*N_];       // (x,y,z,sq)
__device__ int   g_knn[B_*NP_*NS_];
__device__ __align__(16) float g_P [4194304];    // 65536 x 64   pts @ W0[3:]
__device__ __align__(16) float g_Y1[33554432];   // blocked 4096 x 16 x 128 x 4
__device__ __align__(16) float g_Y2[33554432];   // blocked 4096 x 16 x 128 x 4
__device__ __align__(16) float g_Mx[B_*NP_*128]; // raw per-(query,ch) max of layer-3 out
__device__ __align__(16) float g_Mn[B_*NP_*128]; // raw per-(query,ch) min
__device__ float g_psum[4096*128];
__device__ float g_psq [4096*128];
__device__ float g_scale[3][128];
__device__ float g_shift[3][128];
__device__ __align__(16) float g_wt0[67*64];
__device__ __align__(16) float g_wt1[64*64];
__device__ __align__(16) float g_wt2[64*128];
__device__ int g_prog[16];   // FPS progress per batch (queries completed)
__device__ int g_done;       // xyzw table done counter (16 = ready)

// ------------------------- f32x2 packed helpers -------------------------
__device__ __forceinline__ void fma2(ull& d, ull a, ull b) {
    asm("fma.rn.f32x2 %0, %1, %2, %0;" : "+l"(d) : "l"(a), "l"(b));
}
__device__ __forceinline__ ull pk2(float x) {
    ull u;
    asm("mov.b64 %0, {%1, %2};" : "=l"(u) : "f"(x), "f"(x));
    return u;
}
__device__ __forceinline__ float2 up2(ull u) {
    float2 f;
    asm("mov.b64 {%0, %1}, %2;" : "=f"(f.x), "=f"(f.y) : "l"(u));
    return f;
}
__device__ __forceinline__ unsigned fkey(float v) {
    unsigned u = __float_as_uint(v);
    return u ^ (unsigned)(((int)u >> 31) | 0x80000000);
}

// ------------------------- init: transpose weights + reset flags -------------------------
__global__ void k_init(const float* __restrict__ w0, const float* __restrict__ w1,
                       const float* __restrict__ w2) {
    int t = blockIdx.x * blockDim.x + threadIdx.x;
    int stride = gridDim.x * blockDim.x;
    if (blockIdx.x == 0) {
        if (threadIdx.x < 16) g_prog[threadIdx.x] = 0;
        if (threadIdx.x == 16) g_done = 0;
    }
    for (int l = t; l < 64*67; l += stride) { int oc = l / 67, k = l - oc*67; g_wt0[k*64 + oc] = w0[l]; }
    for (int l = t; l < 64*64; l += stride) { int oc = l >> 6, k = l & 63;    g_wt1[k*64 + oc] = w1[l]; }
    for (int l = t; l < 128*64; l += stride){ int oc = l >> 6, k = l & 63;    g_wt2[k*128 + oc] = w2[l]; }
}

// ---------- fused front: FPS(+xyzw) blocks 0-15 | P blocks 16-143 | kNN blocks 144+ --------
#define GBAR() asm volatile("bar.sync %0, 128;" :: "r"(gid + 1) : "memory")

__global__ __launch_bounds__(1024)
void k_front(const float* __restrict__ xyz, const float* __restrict__ pts,
             float* __restrict__ out) {
    extern __shared__ unsigned dynsm[];
    int blk = blockIdx.x, t = threadIdx.x;

    if (blk < 16) {
        // ---- FPS (+ builds xyzw table for its batch). Guaranteed wave-1 resident.
        int b = blk;
        int lane = t & 31, w = t >> 5;
        unsigned* sv = dynsm;               // [2][32]
        int*      si_ = (int*)(dynsm + 64); // [2][32]
        const float* X = xyz + (size_t)b * N_ * 3;
        float px[4], py[4], pz[4], dd[4];
#pragma unroll
        for (int j = 0; j < 4; j++) {
            int n = t*4 + j;
            px[j] = X[n*3]; py[j] = X[n*3+1]; pz[j] = X[n*3+2];
            dd[j] = 1e10f;
            float sq = __fadd_rn(__fadd_rn(__fmul_rn(px[j],px[j]), __fmul_rn(py[j],py[j])),
                                 __fmul_rn(pz[j],pz[j]));
            g_xyzw[(size_t)b * N_ + n] = make_float4(px[j], py[j], pz[j], sq);
        }
        __threadfence();
        __syncthreads();
        if (t == 0) atomicAdd(&g_done, 1);

        float ccx = X[0], ccy = X[1], ccz = X[2];
        float* nx = g_newxyz + (size_t)b * NP_ * 3;
        float* ox = out + (size_t)b * NP_ * 3;

        for (int i = 0; i < NP_; i++) {
            if (t == 0) {
                nx[i*3] = ccx; nx[i*3+1] = ccy; nx[i*3+2] = ccz;
                ox[i*3] = ccx; ox[i*3+1] = ccy; ox[i*3+2] = ccz;
                if ((i & 7) == 7) {           // publish progress (i=1023 publishes 1024)
                    __threadfence();
                    atomicExch(&g_prog[b], i + 1);
                }
            }
            float bv = -1.0f; int bi = 0;
#pragma unroll
            for (int j = 0; j < 4; j++) {
                float dx = __fsub_rn(px[j], ccx);
                float dy = __fsub_rn(py[j], ccy);
                float dz = __fsub_rn(pz[j], ccz);
                float d  = __fadd_rn(__fadd_rn(__fmul_rn(dx,dx), __fmul_rn(dy,dy)), __fmul_rn(dz,dz));
                dd[j] = fminf(dd[j], d);
                if (dd[j] > bv) { bv = dd[j]; bi = t*4 + j; }
            }
            unsigned kv   = __float_as_uint(bv);
            unsigned vmax = __reduce_max_sync(0xffffffffu, kv);
            unsigned cand = (kv == vmax) ? (unsigned)bi : 0xffffffffu;
            unsigned imin = __reduce_min_sync(0xffffffffu, cand);
            int p = i & 1;
            if (lane == 0) { sv[p*32 + w] = vmax; si_[p*32 + w] = (int)imin; }
            __syncthreads();
            unsigned kv2 = sv[p*32 + lane];
            int      ii  = si_[p*32 + lane];
            unsigned vm2 = __reduce_max_sync(0xffffffffu, kv2);
            unsigned c2  = (kv2 == vm2) ? (unsigned)ii : 0xffffffffu;
            unsigned win = __reduce_min_sync(0xffffffffu, c2);
            const float* Pp = X + (size_t)win * 3;
            ccx = Pp[0]; ccy = Pp[1]; ccz = Pp[2];
        }
        return;
    }

    if (blk < 144) {
        // ---- P = pts @ W0[3:,:]
        float* ws = (float*)dynsm;
        for (int i = t; i < 4096; i += 1024) ws[i] = g_wt0[192 + i];
        __syncthreads();
        int row  = (blk - 16) * 512 + (t >> 1);
        int half = (t & 1) * 32;
        const float4* xr = (const float4*)(pts + (size_t)row * 64);
        ull acc2[16];
#pragma unroll
        for (int p = 0; p < 16; p++) acc2[p] = 0ull;
        float4 a0 = __ldg(&xr[0]);
        float4 a1 = __ldg(&xr[1]);
#pragma unroll 1
        for (int kc = 0; kc < 16; kc++) {
            float4 xv = a0; a0 = a1;
            a1 = __ldg(&xr[(kc < 14) ? (kc + 2) : 15]);
            float xs[4] = {xv.x, xv.y, xv.z, xv.w};
#pragma unroll
            for (int kk = 0; kk < 4; kk++) {
                ull xk2 = pk2(xs[kk]);
                const ulonglong2* wr = (const ulonglong2*)(ws + (kc*4 + kk)*64 + half);
#pragma unroll
                for (int p = 0; p < 8; p++) {
                    ulonglong2 wv = wr[p];
                    fma2(acc2[p*2],   xk2, wv.x);
                    fma2(acc2[p*2+1], xk2, wv.y);
                }
            }
        }
        ulonglong2* po = (ulonglong2*)(g_P + (size_t)row * 64 + half);
#pragma unroll
        for (int p = 0; p < 8; p++) po[p] = make_ulonglong2(acc2[2*p], acc2[2*p+1]);
        return;
    }

    // ---- kNN: 8 queries per block, one per 128-thread sub-group (named barriers)
    {
        int gid = t >> 7, tl = t & 127;
        int q = (blk - 144) * 8 + gid;
        int b = q >> 10, m = q & 1023;
        int lane = tl & 31, w = tl >> 5;
        unsigned* G     = dynsm + gid * 2192;
        unsigned* hist  = G;                 // 2048
        unsigned* candk = G + 2048;          // 64
        int*      candi = (int*)(G + 2112);  // 64
        unsigned* sw    = G + 2176;          // 4
        unsigned* spiv  = G + 2180;          // 3
        int*      candn = (int*)(G + 2183);  // 1

        if (tl == 0) {
            while (atomicAdd(&g_done, 0) < 16) __nanosleep(256);
            while (atomicAdd(&g_prog[b], 0) < m + 1) __nanosleep(128);
        }
        GBAR();

        const float4* X4 = g_xyzw + (size_t)b * N_;
        float qx = __ldcg(&g_newxyz[(size_t)q*3]);
        float qy = __ldcg(&g_newxyz[(size_t)q*3+1]);
        float qz = __ldcg(&g_newxyz[(size_t)q*3+2]);
        float sqn = __fadd_rn(__fadd_rn(__fmul_rn(qx,qx), __fmul_rn(qy,qy)), __fmul_rn(qz,qz));

        unsigned key[32];
#pragma unroll
        for (int i = 0; i < 32; i++) {
            float4 v = __ldg(&X4[i*128 + tl]);
            float dot = __fadd_rn(__fadd_rn(__fmul_rn(qx,v.x), __fmul_rn(qy,v.y)), __fmul_rn(qz,v.z));
            float d2  = __fsub_rn(__fadd_rn(sqn, v.w), __fmul_rn(2.0f, dot));
            key[i] = fkey(d2);
        }

        for (int j = tl; j < 2048; j += 128) hist[j] = 0;
        if (tl == 0) *candn = 0;
        GBAR();
#pragma unroll
        for (int i = 0; i < 32; i++) atomicAdd(&hist[key[i] >> 21], 1u);
        GBAR();
        unsigned s = 0;
#pragma unroll
        for (int j = 0; j < 16; j++) s += hist[tl*16 + j];
        unsigned inc = s;
#pragma unroll
        for (int o = 1; o < 32; o <<= 1) { unsigned nn = __shfl_up_sync(~0u, inc, o); if (lane >= o) inc += nn; }
        if (lane == 31) sw[w] = inc;
        GBAR();
        unsigned wbase = 0;
        for (int j = 0; j < w; j++) wbase += sw[j];
        unsigned base = wbase + inc - s;
        if (base < 32 && base + s >= 32) {
            unsigned cum = base;
#pragma unroll
            for (int j = 0; j < 16; j++) {
                unsigned c = hist[tl*16 + j];
                if (cum + c >= 32) { spiv[0] = tl*16 + j; spiv[1] = cum; spiv[2] = c; break; }
                cum += c;
            }
        }
        GBAR();
        unsigned pb1 = spiv[0];
        unsigned cb  = spiv[1];
        unsigned pc  = spiv[2];
        unsigned Kstar, width;

        if (pc > 64) {
            unsigned need2 = 32 - cb;
            for (int j = tl; j < 2048; j += 128) hist[j] = 0;
            GBAR();
#pragma unroll
            for (int i = 0; i < 32; i++)
                if ((key[i] >> 21) == pb1) atomicAdd(&hist[(key[i] >> 10) & 2047], 1u);
            GBAR();
            s = 0;
#pragma unroll
            for (int j = 0; j < 16; j++) s += hist[tl*16 + j];
            inc = s;
#pragma unroll
            for (int o = 1; o < 32; o <<= 1) { unsigned nn = __shfl_up_sync(~0u, inc, o); if (lane >= o) inc += nn; }
            if (lane == 31) sw[w] = inc;
            GBAR();
            wbase = 0;
            for (int j = 0; j < w; j++) wbase += sw[j];
            base = wbase + inc - s;
            if (base < need2 && base + s >= need2) {
                unsigned cum = base;
#pragma unroll
                for (int j = 0; j < 16; j++) {
                    unsigned c = hist[tl*16 + j];
                    if (cum + c >= need2) { spiv[0] = tl*16 + j; spiv[1] = cum; break; }
                    cum += c;
                }
            }
            GBAR();
            Kstar = (pb1 << 21) | (spiv[0] << 10);
            width = 1u << 10;
            cb = cb + spiv[1];
            GBAR();
        } else {
            Kstar = pb1 << 21;
            width = 1u << 21;
        }

        int ct = 0;
#pragma unroll
        for (int i = 0; i < 32; i++) ct += (key[i] < Kstar);
        int inci = ct;
#pragma unroll
        for (int o = 1; o < 32; o <<= 1) { int nn = __shfl_up_sync(~0u, inci, o); if (lane >= o) inci += nn; }
        if (lane == 31) sw[w] = (unsigned)inci;
        GBAR();
        int wb = 0;
        for (int j = 0; j < w; j++) wb += (int)sw[j];
        int slot = wb + inci - ct;
        int* KO = g_knn + (size_t)q * NS_;
#pragma unroll
        for (int i = 0; i < 32; i++) {
            unsigned k = key[i];
            if (k < Kstar) { KO[slot++] = i*128 + tl; }
            else if (k - Kstar < width) {
                int p = atomicAdd(candn, 1);
                if (p < 64) { candk[p] = k; candi[p] = i*128 + tl; }
            }
        }
        GBAR();
        int L = *candn; if (L > 64) L = 64;
        int need = 32 - (int)cb;
        if (tl < L) {
            unsigned mk = candk[tl]; int mi = candi[tl];
            int rank = 0;
            for (int j = 0; j < L; j++) {
                unsigned kj = candk[j];
                rank += (kj < mk) || (kj == mk && candi[j] < mi);
            }
            if (rank < need) KO[cb + rank] = mi;
        }
    }
}

// ---------- layer 1: gather(P) + rel_xyz @ W0[:3], half-row per thread (256 thr) -----------
__global__ __launch_bounds__(256)
void k_gemm1(const float* __restrict__ xyz) {
    __shared__ float ws[192];
    __shared__ float tile[64*65];
    __shared__ float ps[256], pq[256];
    int t = threadIdx.x;
    int row = t & 127, half = t >> 7;
    for (int i = t; i < 192; i += 256) ws[i] = g_wt0[i];
    __syncthreads();

    size_t r = (size_t)blockIdx.x * 128 + row;
    int b  = (int)(r >> 15);
    int bm = (int)(r >> 5);
    int j  = g_knn[r];
    const float* Pt = xyz + ((size_t)b * N_ + j) * 3;
    const float* Q  = g_newxyz + (size_t)bm * 3;
    float f0 = Pt[0] - Q[0], f1 = Pt[1] - Q[1], f2 = Pt[2] - Q[2];

    const float4* prow = (const float4*)(g_P + ((size_t)b * N_ + j) * 64) + half*8;
    float4 pv[8];
#pragma unroll
    for (int kc = 0; kc < 8; kc++) pv[kc] = __ldg(&prow[kc]);

    float acc[32];
    float4* yo = (float4*)g_Y1 + (size_t)blockIdx.x * 2048 + row;
#pragma unroll
    for (int kc = 0; kc < 8; kc++) {
        int o = half*32 + kc*4;
        float4 st;
        st.x = fmaf(f2, ws[128+o],   fmaf(f1, ws[64+o],   fmaf(f0, ws[o],   pv[kc].x)));
        st.y = fmaf(f2, ws[128+o+1], fmaf(f1, ws[64+o+1], fmaf(f0, ws[o+1], pv[kc].y)));
        st.z = fmaf(f2, ws[128+o+2], fmaf(f1, ws[64+o+2], fmaf(f0, ws[o+2], pv[kc].z)));
        st.w = fmaf(f2, ws[128+o+3], fmaf(f1, ws[64+o+3], fmaf(f0, ws[o+3], pv[kc].w)));
        yo[(half*8 + kc)*128] = st;
        acc[kc*4]   = st.x; acc[kc*4+1] = st.y;
        acc[kc*4+2] = st.z; acc[kc*4+3] = st.w;
    }

    float psa = 0.f, pqa = 0.f;
#pragma unroll
    for (int ph = 0; ph < 2; ph++) {
        if ((row >> 6) == ph) {
#pragma unroll
            for (int o = 0; o < 32; o++) tile[(row & 63)*65 + half*32 + o] = acc[o];
        }
        __syncthreads();
        int c = t & 63, g = t >> 6;
#pragma unroll 4
        for (int rr = g*16; rr < g*16 + 16; rr++) {
            float v = tile[rr*65 + c];
            psa += v; pqa = fmaf(v, v, pqa);
        }
        __syncthreads();
    }
    ps[t] = psa; pq[t] = pqa;
    __syncthreads();
    if (t < 64) {
        g_psum[(size_t)blockIdx.x*64 + t] = ps[t] + ps[64+t] + ps[128+t] + ps[192+t];
        g_psq [(size_t)blockIdx.x*64 + t] = pq[t] + pq[64+t] + pq[128+t] + pq[192+t];
    }
}

// ------------------------- layer 2: BN0+ReLU(Y1) @ W1 (f32x2, blocked, 128 thr) -----------
__global__ __launch_bounds__(128)
void k_gemm2() {
    extern __shared__ __align__(16) float dyn[];
    float* ws   = dyn;
    float* tile = dyn;
    float* sc   = dyn + 8320;
    float* sh   = sc + 64;
    float* ps   = sh + 64;
    float* pq   = ps + 128;
    int t = threadIdx.x;
    for (int i = t; i < 4096; i += 128) ws[i] = g_wt1[i];
    if (t < 64) { sc[t] = g_scale[0][t]; sh[t] = g_shift[0][t]; }
    __syncthreads();

    const float4* xr = (const float4*)g_Y1 + (size_t)blockIdx.x * 2048 + t;
    ull acc2[32];
#pragma unroll
    for (int p = 0; p < 32; p++) acc2[p] = 0ull;

    float4 a0 = xr[0];
    float4 a1 = xr[128];
#pragma unroll 1
    for (int kc = 0; kc < 16; kc++) {
        float4 yv = a0; a0 = a1;
        a1 = xr[((kc < 14) ? (kc + 2) : 15) * 128];
        int kb = kc * 4;
        float ys[4] = {yv.x, yv.y, yv.z, yv.w};
#pragma unroll
        for (int kk = 0; kk < 4; kk++) {
            float xk = fmaxf(fmaf(ys[kk], sc[kb+kk], sh[kb+kk]), 0.f);
            ull xk2 = pk2(xk);
            const ulonglong2* wr = (const ulonglong2*)(ws + (kb+kk)*64);
#pragma unroll
            for (int p = 0; p < 16; p++) {
                ulonglong2 wv = wr[p];
                fma2(acc2[2*p],   xk2, wv.x);
                fma2(acc2[2*p+1], xk2, wv.y);
            }
        }
    }
    ulonglong2* yo = (ulonglong2*)((float4*)g_Y2 + (size_t)blockIdx.x * 2048 + t);
#pragma unroll
    for (int kc = 0; kc < 16; kc++)
        yo[kc*128] = make_ulonglong2(acc2[2*kc], acc2[2*kc+1]);

    __syncthreads();
#pragma unroll
    for (int p = 0; p < 32; p++) {
        float2 f = up2(acc2[p]);
        tile[t*65 + 2*p]     = f.x;
        tile[t*65 + 2*p + 1] = f.y;
    }
    __syncthreads();
    int c = t & 63, g = t >> 6;
    float sa = 0.f, qa = 0.f;
#pragma unroll 4
    for (int rr = g*64; rr < g*64 + 64; rr++) {
        float v = tile[rr*65 + c];
        sa += v; qa = fmaf(v, v, qa);
    }
    ps[g*64 + c] = sa; pq[g*64 + c] = qa;
    __syncthreads();
    if (t < 64) {
        g_psum[(size_t)blockIdx.x*64 + t] = ps[t] + ps[64 + t];
        g_psq [(size_t)blockIdx.x*64 + t] = pq[t] + pq[64 + t];
    }
}

// --------- layer 3: BN1+ReLU(Y2) @ W2 -> 128 ch; NO Y3 store, per-query raw min/max --------
__global__ __launch_bounds__(256)
void k_gemm3() {
    extern __shared__ __align__(16) float dyn[];
    float* ws   = dyn;
    float* tile = dyn;
    float* sc   = dyn + 16512;
    float* sh   = sc + 64;
    float* ps   = sh + 64;
    float* pq   = ps + 256;
    int t = threadIdx.x;
    for (int i = t; i < 64*128; i += 256) ws[i] = g_wt2[i];
    if (t < 64) { sc[t] = g_scale[1][t]; sh[t] = g_shift[1][t]; }
    __syncthreads();

    int row  = t & 127;
    int half = (t >> 7) * 64;
    const float4* xr = (const float4*)g_Y2 + (size_t)blockIdx.x * 2048 + row;
    ull acc2[32];
#pragma unroll
    for (int p = 0; p < 32; p++) acc2[p] = 0ull;

    float4 a0 = xr[0];
    float4 a1 = xr[128];
#pragma unroll 1
    for (int kc = 0; kc < 16; kc++) {
        float4 yv = a0; a0 = a1;
        a1 = xr[((kc < 14) ? (kc + 2) : 15) * 128];
        int kb = kc * 4;
        float ys[4] = {yv.x, yv.y, yv.z, yv.w};
#pragma unroll
        for (int kk = 0; kk < 4; kk++) {
            float xk = fmaxf(fmaf(ys[kk], sc[kb+kk], sh[kb+kk]), 0.f);
            ull xk2 = pk2(xk);
            const ulonglong2* wr = (const ulonglong2*)(ws + (kb+kk)*128 + half);
#pragma unroll
            for (int p = 0; p < 16; p++) {
                ulonglong2 wv = wr[p];
                fma2(acc2[2*p],   xk2, wv.x);
                fma2(acc2[2*p+1], xk2, wv.y);
            }
        }
    }

    __syncthreads();
#pragma unroll
    for (int p = 0; p < 32; p++) {
        float2 f = up2(acc2[p]);
        tile[row*129 + half + 2*p]     = f.x;
        tile[row*129 + half + 2*p + 1] = f.y;
    }
    __syncthreads();

    int c = t & 127, g = t >> 7;
    float sa = 0.f, qa = 0.f;
#pragma unroll 4
    for (int rr = g*64; rr < g*64 + 64; rr++) {
        float v = tile[rr*129 + c];
        sa += v; qa = fmaf(v, v, qa);
    }
    ps[g*128 + c] = sa; pq[g*128 + c] = qa;

#pragma unroll
    for (int e = t; e < 512; e += 256) {
        int qi = e >> 7, ch = e & 127;
        int r0 = qi * 32;
        float mx = tile[r0*129 + ch], mn = mx;
#pragma unroll 4
        for (int rr = r0 + 1; rr < r0 + 32; rr++) {
            float v = tile[rr*129 + ch];
            mx = fmaxf(mx, v); mn = fminf(mn, v);
        }
        g_Mx[(size_t)blockIdx.x*512 + e] = mx;
        g_Mn[(size_t)blockIdx.x*512 + e] = mn;
    }
    __syncthreads();
    if (t < 128) {
        g_psum[(size_t)blockIdx.x*128 + t] = ps[t] + ps[128 + t];
        g_psq [(size_t)blockIdx.x*128 + t] = pq[t] + pq[128 + t];
    }
}

// ------------------------- finalize BN stats: one block per channel -----------------------
__global__ __launch_bounds__(256)
void k_fin(const float* __restrict__ gma, const float* __restrict__ beta,
           int OC, int layer) {
    int c = blockIdx.x, t = threadIdx.x;
    float s = 0.f, s2 = 0.f;
    for (int i = t; i < 4096; i += 256) {
        s  += g_psum[(size_t)i * OC + c];
        s2 += g_psq [(size_t)i * OC + c];
    }
#pragma unroll
    for (int off = 16; off; off >>= 1) {
        s  += __shfl_down_sync(0xffffffffu, s, off);
        s2 += __shfl_down_sync(0xffffffffu, s2, off);
    }
    __shared__ float a[8], a2[8];
    if ((t & 31) == 0) { a[t>>5] = s; a2[t>>5] = s2; }
    __syncthreads();
    if (t == 0) {
        double S = 0.0, S2 = 0.0;
#pragma unroll
        for (int wb = 0; wb < 8; wb++) { S += (double)a[wb]; S2 += (double)a2[wb]; }
        double inv  = 1.0 / (double)NROWS;
        double mean = S * inv;
        double var  = S2 * inv - mean * mean;
        float scale = (float)((double)gma[c] * rsqrt(var + 1e-5));
        float shift = (float)((double)beta[c] - mean * (double)scale);
        g_scale[layer][c] = scale;
        g_shift[layer][c] = shift;
    }
}

// ---------- pool: BN2 applied to raw min/max (monotone-exact) + transposed write -----------
__global__ __launch_bounds__(128)
void k_pool(float* __restrict__ out) {
    __shared__ float sm[128*33];
    int t = threadIdx.x;
    float sc = g_scale[2][t], sh = g_shift[2][t];
    int q0 = blockIdx.x * 32;
    int b  = q0 >> 10;
    const float* src = (sc > 0.f) ? g_Mx : g_Mn;
#pragma unroll 4
    for (int qi = 0; qi < 32; qi++) {
        float v = src[(size_t)(q0 + qi)*128 + t];
        sm[t*33 + qi] = fmaxf(fmaf(v, sc, sh), 0.f);
    }
    __syncthreads();
    int mloc = t & 31, og = t >> 5;
    int mg = q0 & 1023;
#pragma unroll
    for (int i = 0; i < 32; i++) {
        int oc = og + i*4;
        out[49152 + ((size_t)(b*128 + oc))*1024 + mg + mloc] = sm[oc*33 + mloc];
    }
}

// ------------------------- launch --------------------------------------------------------
extern "C" void kernel_launch(void* const* d_in, const int* in_sizes, int n_in,
                              void* d_out, int out_size) {
    const float* xyz = (const float*)d_in[0];
    const float* pts = (const float*)d_in[1];
    const float* w0  = (const float*)d_in[2];
    const float* g0  = (const float*)d_in[4];
    const float* be0 = (const float*)d_in[5];
    const float* w1  = (const float*)d_in[6];
    const float* g1  = (const float*)d_in[8];
    const float* be1 = (const float*)d_in[9];
    const float* w2  = (const float*)d_in[10];
    const float* g2  = (const float*)d_in[12];
    const float* be2 = (const float*)d_in[13];
    float* out = (float*)d_out;

    const int SMEMF = 2192 * 8 * 4;  // 70144 B (knn groups; P path uses first 16KB)
    const int SMEM2 = 8704 * 4;      // 34816 B
    const int SMEM3 = 17152 * 4;     // 68608 B
    cudaFuncSetAttribute(k_front, cudaFuncAttributeMaxDynamicSharedMemorySize, SMEMF);
    cudaFuncSetAttribute(k_gemm2, cudaFuncAttributeMaxDynamicSharedMemorySize, SMEM2);
    cudaFuncSetAttribute(k_gemm3, cudaFuncAttributeMaxDynamicSharedMemorySize, SMEM3);

    k_init<<<64, 256>>>(w0, w1, w2);
    k_front<<<16 + 128 + 2048, 1024, SMEMF>>>(xyz, pts, out);

    k_gemm1<<<NROWS/128, 256>>>(xyz);
    k_fin<<<64, 256>>>(g0, be0, 64, 0);

    k_gemm2<<<NROWS/128, 128, SMEM2>>>();
    k_fin<<<64, 256>>>(g1, be1, 64, 1);

    k_gemm3<<<NROWS/128, 256, SMEM3>>>();
    k_fin<<<128, 256>>>(g2, be2, 128, 2);

    k_pool<<<B_*NP_/32, 128>>>(out);
}

// round 15
// speedup vs baseline: 1.0480x; 1.0426x over previous
#include <cuda_runtime.h>
#include <math_constants.h>

#define B_   16
#define N_   4096
#define NP_  1024
#define NS_  32
#define NROWS 524288   // B_*NP_*NS_

typedef unsigned long long ull;

// ------------------------- static device scratch (no allocation) -------------------------
__device__ __align__(16) float g_newxyz[B_*NP_*3];
__device__ __align__(16) float4 g_xyzw[B_*N_];       // (x,y,z,sq)
__device__ int   g_knn[B_*NP_*NS_];
__device__ __align__(16) float g_P [4194304];    // 65536 x 64   pts @ W0[3:]
__device__ __align__(16) float g_Y1[33554432];   // blocked 4096 x 16 x 128 x 4
__device__ __align__(16) float g_Y2[33554432];   // blocked 4096 x 16 x 128 x 4
__device__ __align__(16) float g_Mx[B_*NP_*128]; // raw per-(query,ch) max of layer-3 out
__device__ __align__(16) float g_Mn[B_*NP_*128]; // raw per-(query,ch) min
__device__ __align__(16) float g_psum[128*4096]; // channel-major: [c][bid]
__device__ __align__(16) float g_psq [128*4096];
__device__ float g_scale[3][128];
__device__ float g_shift[3][128];
__device__ __align__(16) float g_wt0[67*64];
__device__ __align__(16) float g_wt1[64*64];
__device__ __align__(16) float g_wt2[64*128];

// ------------------------- f32x2 packed helpers -------------------------
__device__ __forceinline__ void fma2(ull& d, ull a, ull b) {
    asm("fma.rn.f32x2 %0, %1, %2, %0;" : "+l"(d) : "l"(a), "l"(b));
}
__device__ __forceinline__ ull pk2(float x) {
    ull u;
    asm("mov.b64 %0, {%1, %2};" : "=l"(u) : "f"(x), "f"(x));
    return u;
}
__device__ __forceinline__ float2 up2(ull u) {
    float2 f;
    asm("mov.b64 {%0, %1}, %2;" : "=f"(f.x), "=f"(f.y) : "l"(u));
    return f;
}

// ------------------------- init: transpose weights to [K][OC] -------------------------
__global__ void k_init(const float* __restrict__ w0, const float* __restrict__ w1,
                       const float* __restrict__ w2) {
    int t = blockIdx.x * blockDim.x + threadIdx.x;
    int stride = gridDim.x * blockDim.x;
    for (int l = t; l < 64*67; l += stride) { int oc = l / 67, k = l - oc*67; g_wt0[k*64 + oc] = w0[l]; }
    for (int l = t; l < 64*64; l += stride) { int oc = l >> 6, k = l & 63;    g_wt1[k*64 + oc] = w1[l]; }
    for (int l = t; l < 128*64; l += stride){ int oc = l >> 6, k = l & 63;    g_wt2[k*128 + oc] = w2[l]; }
}

// ------------------------- fused front: P precompute | xyzw table | FPS -------------------
__global__ __launch_bounds__(1024)
void k_front(const float* __restrict__ xyz, const float* __restrict__ pts,
             float* __restrict__ out) {
    __shared__ __align__(16) float ws[4096];
    __shared__ unsigned sv[2][32]; __shared__ int si_[2][32];
    int blk = blockIdx.x, t = threadIdx.x;

    if (blk < 128) {
        // ---- P = pts @ W0[3:,:]
        for (int i = t; i < 4096; i += 1024) ws[i] = g_wt0[192 + i];
        __syncthreads();
        int row  = blk * 512 + (t >> 1);
        int half = (t & 1) * 32;
        const float4* xr = (const float4*)(pts + (size_t)row * 64);
        ull acc2[16];
#pragma unroll
        for (int p = 0; p < 16; p++) acc2[p] = 0ull;
        float4 a0 = __ldg(&xr[0]);
        float4 a1 = __ldg(&xr[1]);
#pragma unroll 1
        for (int kc = 0; kc < 16; kc++) {
            float4 xv = a0; a0 = a1;
            a1 = __ldg(&xr[(kc < 14) ? (kc + 2) : 15]);
            float xs[4] = {xv.x, xv.y, xv.z, xv.w};
#pragma unroll
            for (int kk = 0; kk < 4; kk++) {
                ull xk2 = pk2(xs[kk]);
                const ulonglong2* wr = (const ulonglong2*)(ws + (kc*4 + kk)*64 + half);
#pragma unroll
                for (int p = 0; p < 8; p++) {
                    ulonglong2 wv = wr[p];
                    fma2(acc2[p*2],   xk2, wv.x);
                    fma2(acc2[p*2+1], xk2, wv.y);
                }
            }
        }
        ulonglong2* po = (ulonglong2*)(g_P + (size_t)row * 64 + half);
#pragma unroll
        for (int p = 0; p < 8; p++) po[p] = make_ulonglong2(acc2[2*p], acc2[2*p+1]);
        return;
    }
    if (blk < 192) {
        int n = (blk - 128) * 1024 + t;
        const float* X = xyz + (size_t)n * 3;
        float x = X[0], y = X[1], z = X[2];
        float sq = __fadd_rn(__fadd_rn(__fmul_rn(x,x), __fmul_rn(y,y)), __fmul_rn(z,z));
        g_xyzw[n] = make_float4(x, y, z, sq);
        return;
    }

    // ---- FPS: single barrier per iteration (double-buffered winner slots)
    int b = blk - 192;
    int lane = t & 31, w = t >> 5;
    const float* X = xyz + (size_t)b * N_ * 3;
    float px[4], py[4], pz[4], dd[4];
#pragma unroll
    for (int j = 0; j < 4; j++) {
        int n = t*4 + j;
        px[j] = X[n*3]; py[j] = X[n*3+1]; pz[j] = X[n*3+2];
        dd[j] = 1e10f;
    }
    float ccx = X[0], ccy = X[1], ccz = X[2];
    float* nx = g_newxyz + (size_t)b * NP_ * 3;
    float* ox = out + (size_t)b * NP_ * 3;

    for (int i = 0; i < NP_; i++) {
        if (t == 0) {
            nx[i*3] = ccx; nx[i*3+1] = ccy; nx[i*3+2] = ccz;
            ox[i*3] = ccx; ox[i*3+1] = ccy; ox[i*3+2] = ccz;
        }
        float bv = -1.0f; int bi = 0;
#pragma unroll
        for (int j = 0; j < 4; j++) {
            float dx = __fsub_rn(px[j], ccx);
            float dy = __fsub_rn(py[j], ccy);
            float dz = __fsub_rn(pz[j], ccz);
            float d  = __fadd_rn(__fadd_rn(__fmul_rn(dx,dx), __fmul_rn(dy,dy)), __fmul_rn(dz,dz));
            dd[j] = fminf(dd[j], d);
            if (dd[j] > bv) { bv = dd[j]; bi = t*4 + j; }
        }
        unsigned kv   = __float_as_uint(bv);
        unsigned vmax = __reduce_max_sync(0xffffffffu, kv);
        unsigned cand = (kv == vmax) ? (unsigned)bi : 0xffffffffu;
        unsigned imin = __reduce_min_sync(0xffffffffu, cand);
        int p = i & 1;
        if (lane == 0) { sv[p][w] = vmax; si_[p][w] = (int)imin; }
        __syncthreads();
        unsigned kv2 = sv[p][lane];
        int      ii  = si_[p][lane];
        unsigned vm2 = __reduce_max_sync(0xffffffffu, kv2);
        unsigned c2  = (kv2 == vm2) ? (unsigned)ii : 0xffffffffu;
        unsigned win = __reduce_min_sync(0xffffffffu, c2);
        const float* Pp = X + (size_t)win * 3;
        ccx = Pp[0]; ccy = Pp[1]; ccz = Pp[2];
    }
}

__device__ __forceinline__ unsigned fkey(float v) {
    unsigned u = __float_as_uint(v);
    return u ^ (unsigned)(((int)u >> 31) | 0x80000000);
}

// ------------------------- kNN: histogram radix-select (one block / query) -----------------
__global__ __launch_bounds__(128)
void k_knn() {
    int q = blockIdx.x, b = q >> 10, t = threadIdx.x;
    int lane = t & 31, w = t >> 5;
    const float4* X4 = g_xyzw + (size_t)b * N_;
    const float* Q = g_newxyz + (size_t)q * 3;
    float qx = Q[0], qy = Q[1], qz = Q[2];
    float sqn = __fadd_rn(__fadd_rn(__fmul_rn(qx,qx), __fmul_rn(qy,qy)), __fmul_rn(qz,qz));

    unsigned key[32];
#pragma unroll
    for (int i = 0; i < 32; i++) {
        float4 v = __ldg(&X4[i*128 + t]);
        float dot = __fadd_rn(__fadd_rn(__fmul_rn(qx,v.x), __fmul_rn(qy,v.y)), __fmul_rn(qz,v.z));
        float d2  = __fsub_rn(__fadd_rn(sqn, v.w), __fmul_rn(2.0f, dot));
        key[i] = fkey(d2);
    }

    __shared__ unsigned hist[2048];
    __shared__ unsigned sw[4];
    __shared__ unsigned spiv[3];
    __shared__ unsigned candk[64];
    __shared__ int candi[64];
    __shared__ int candn;

    for (int j = t; j < 2048; j += 128) hist[j] = 0;
    if (t == 0) candn = 0;
    __syncthreads();
#pragma unroll
    for (int i = 0; i < 32; i++) atomicAdd(&hist[key[i] >> 21], 1u);
    __syncthreads();
    unsigned s = 0;
#pragma unroll
    for (int j = 0; j < 16; j++) s += hist[t*16 + j];
    unsigned inc = s;
#pragma unroll
    for (int o = 1; o < 32; o <<= 1) { unsigned nn = __shfl_up_sync(~0u, inc, o); if (lane >= o) inc += nn; }
    if (lane == 31) sw[w] = inc;
    __syncthreads();
    unsigned wbase = 0;
    for (int j = 0; j < w; j++) wbase += sw[j];
    unsigned base = wbase + inc - s;
    if (base < 32 && base + s >= 32) {
        unsigned cum = base;
#pragma unroll
        for (int j = 0; j < 16; j++) {
            unsigned c = hist[t*16 + j];
            if (cum + c >= 32) { spiv[0] = t*16 + j; spiv[1] = cum; spiv[2] = c; break; }
            cum += c;
        }
    }
    __syncthreads();
    unsigned pb1 = spiv[0];
    unsigned cb  = spiv[1];
    unsigned pc  = spiv[2];
    unsigned Kstar, width;

    if (pc > 64) {
        unsigned need2 = 32 - cb;
        for (int j = t; j < 2048; j += 128) hist[j] = 0;
        __syncthreads();
#pragma unroll
        for (int i = 0; i < 32; i++)
            if ((key[i] >> 21) == pb1) atomicAdd(&hist[(key[i] >> 10) & 2047], 1u);
        __syncthreads();
        s = 0;
#pragma unroll
        for (int j = 0; j < 16; j++) s += hist[t*16 + j];
        inc = s;
#pragma unroll
        for (int o = 1; o < 32; o <<= 1) { unsigned nn = __shfl_up_sync(~0u, inc, o); if (lane >= o) inc += nn; }
        if (lane == 31) sw[w] = inc;
        __syncthreads();
        wbase = 0;
        for (int j = 0; j < w; j++) wbase += sw[j];
        base = wbase + inc - s;
        if (base < need2 && base + s >= need2) {
            unsigned cum = base;
#pragma unroll
            for (int j = 0; j < 16; j++) {
                unsigned c = hist[t*16 + j];
                if (cum + c >= need2) { spiv[0] = t*16 + j; spiv[1] = cum; break; }
                cum += c;
            }
        }
        __syncthreads();
        Kstar = (pb1 << 21) | (spiv[0] << 10);
        width = 1u << 10;
        cb = cb + spiv[1];
        __syncthreads();
    } else {
        Kstar = pb1 << 21;
        width = 1u << 21;
    }

    int ct = 0;
#pragma unroll
    for (int i = 0; i < 32; i++) ct += (key[i] < Kstar);
    int inci = ct;
#pragma unroll
    for (int o = 1; o < 32; o <<= 1) { int nn = __shfl_up_sync(~0u, inci, o); if (lane >= o) inci += nn; }
    if (lane == 31) sw[w] = (unsigned)inci;
    __syncthreads();
    int wb = 0;
    for (int j = 0; j < w; j++) wb += (int)sw[j];
    int slot = wb + inci - ct;
    int* KO = g_knn + (size_t)q * NS_;
#pragma unroll
    for (int i = 0; i < 32; i++) {
        unsigned k = key[i];
        if (k < Kstar) { KO[slot++] = i*128 + t; }
        else if (k - Kstar < width) {
            int p = atomicAdd(&candn, 1);
            if (p < 64) { candk[p] = k; candi[p] = i*128 + t; }
        }
    }
    __syncthreads();
    int L = candn; if (L > 64) L = 64;
    int need = 32 - (int)cb;
    if (t < L) {
        unsigned mk = candk[t]; int mi = candi[t];
        int rank = 0;
        for (int j = 0; j < L; j++) {
            unsigned kj = candk[j];
            rank += (kj < mk) || (kj == mk && candi[j] < mi);
        }
        if (rank < need) KO[cb + rank] = mi;
    }
}

// ---------- layer 1: gather(P) + rel_xyz @ W0[:3], half-row per thread (256 thr) -----------
__global__ __launch_bounds__(256)
void k_gemm1(const float* __restrict__ xyz) {
    __shared__ float ws[192];
    __shared__ float tile[64*65];
    __shared__ float ps[256], pq[256];
    int t = threadIdx.x;
    int row = t & 127, half = t >> 7;
    for (int i = t; i < 192; i += 256) ws[i] = g_wt0[i];
    __syncthreads();

    size_t r = (size_t)blockIdx.x * 128 + row;
    int b  = (int)(r >> 15);
    int bm = (int)(r >> 5);
    int j  = g_knn[r];
    const float* Pt = xyz + ((size_t)b * N_ + j) * 3;
    const float* Q  = g_newxyz + (size_t)bm * 3;
    float f0 = Pt[0] - Q[0], f1 = Pt[1] - Q[1], f2 = Pt[2] - Q[2];

    const float4* prow = (const float4*)(g_P + ((size_t)b * N_ + j) * 64) + half*8;
    float4 pv[8];
#pragma unroll
    for (int kc = 0; kc < 8; kc++) pv[kc] = __ldg(&prow[kc]);

    float acc[32];
    float4* yo = (float4*)g_Y1 + (size_t)blockIdx.x * 2048 + row;
#pragma unroll
    for (int kc = 0; kc < 8; kc++) {
        int o = half*32 + kc*4;
        float4 st;
        st.x = fmaf(f2, ws[128+o],   fmaf(f1, ws[64+o],   fmaf(f0, ws[o],   pv[kc].x)));
        st.y = fmaf(f2, ws[128+o+1], fmaf(f1, ws[64+o+1], fmaf(f0, ws[o+1], pv[kc].y)));
        st.z = fmaf(f2, ws[128+o+2], fmaf(f1, ws[64+o+2], fmaf(f0, ws[o+2], pv[kc].z)));
        st.w = fmaf(f2, ws[128+o+3], fmaf(f1, ws[64+o+3], fmaf(f0, ws[o+3], pv[kc].w)));
        yo[(half*8 + kc)*128] = st;
        acc[kc*4]   = st.x; acc[kc*4+1] = st.y;
        acc[kc*4+2] = st.z; acc[kc*4+3] = st.w;
    }

    float psa = 0.f, pqa = 0.f;
#pragma unroll
    for (int ph = 0; ph < 2; ph++) {
        if ((row >> 6) == ph) {
#pragma unroll
            for (int o = 0; o < 32; o++) tile[(row & 63)*65 + half*32 + o] = acc[o];
        }
        __syncthreads();
        int c = t & 63, g = t >> 6;
#pragma unroll 4
        for (int rr = g*16; rr < g*16 + 16; rr++) {
            float v = tile[rr*65 + c];
            psa += v; pqa = fmaf(v, v, pqa);
        }
        __syncthreads();
    }
    ps[t] = psa; pq[t] = pqa;
    __syncthreads();
    if (t < 64) {
        g_psum[(size_t)t*4096 + blockIdx.x] = ps[t] + ps[64+t] + ps[128+t] + ps[192+t];
        g_psq [(size_t)t*4096 + blockIdx.x] = pq[t] + pq[64+t] + pq[128+t] + pq[192+t];
    }
}

// ------------------------- layer 2: BN0+ReLU(Y1) @ W1 (f32x2, blocked, 128 thr) -----------
__global__ __launch_bounds__(128)
void k_gemm2() {
    extern __shared__ __align__(16) float dyn[];
    float* ws   = dyn;
    float* tile = dyn;
    float* sc   = dyn + 8320;
    float* sh   = sc + 64;
    float* ps   = sh + 64;
    float* pq   = ps + 128;
    int t = threadIdx.x;
    for (int i = t; i < 4096; i += 128) ws[i] = g_wt1[i];
    if (t < 64) { sc[t] = g_scale[0][t]; sh[t] = g_shift[0][t]; }
    __syncthreads();

    const float4* xr = (const float4*)g_Y1 + (size_t)blockIdx.x * 2048 + t;
    ull acc2[32];
#pragma unroll
    for (int p = 0; p < 32; p++) acc2[p] = 0ull;

    float4 a0 = xr[0];
    float4 a1 = xr[128];
#pragma unroll 1
    for (int kc = 0; kc < 16; kc++) {
        float4 yv = a0; a0 = a1;
        a1 = xr[((kc < 14) ? (kc + 2) : 15) * 128];
        int kb = kc * 4;
        float ys[4] = {yv.x, yv.y, yv.z, yv.w};
#pragma unroll
        for (int kk = 0; kk < 4; kk++) {
            float xk = fmaxf(fmaf(ys[kk], sc[kb+kk], sh[kb+kk]), 0.f);
            ull xk2 = pk2(xk);
            const ulonglong2* wr = (const ulonglong2*)(ws + (kb+kk)*64);
#pragma unroll
            for (int p = 0; p < 16; p++) {
                ulonglong2 wv = wr[p];
                fma2(acc2[2*p],   xk2, wv.x);
                fma2(acc2[2*p+1], xk2, wv.y);
            }
        }
    }
    ulonglong2* yo = (ulonglong2*)((float4*)g_Y2 + (size_t)blockIdx.x * 2048 + t);
#pragma unroll
    for (int kc = 0; kc < 16; kc++)
        yo[kc*128] = make_ulonglong2(acc2[2*kc], acc2[2*kc+1]);

    __syncthreads();
#pragma unroll
    for (int p = 0; p < 32; p++) {
        float2 f = up2(acc2[p]);
        tile[t*65 + 2*p]     = f.x;
        tile[t*65 + 2*p + 1] = f.y;
    }
    __syncthreads();
    int c = t & 63, g = t >> 6;
    float sa = 0.f, qa = 0.f;
#pragma unroll 4
    for (int rr = g*64; rr < g*64 + 64; rr++) {
        float v = tile[rr*65 + c];
        sa += v; qa = fmaf(v, v, qa);
    }
    ps[g*64 + c] = sa; pq[g*64 + c] = qa;
    __syncthreads();
    if (t < 64) {
        g_psum[(size_t)t*4096 + blockIdx.x] = ps[t] + ps[64 + t];
        g_psq [(size_t)t*4096 + blockIdx.x] = pq[t] + pq[64 + t];
    }
}

// --------- layer 3: BN1+ReLU(Y2) @ W2 -> 128 ch; NO Y3 store, per-query raw min/max --------
__global__ __launch_bounds__(256)
void k_gemm3() {
    extern __shared__ __align__(16) float dyn[];
    float* ws   = dyn;
    float* tile = dyn;
    float* sc   = dyn + 16512;
    float* sh   = sc + 64;
    float* ps   = sh + 64;
    float* pq   = ps + 256;
    int t = threadIdx.x;
    for (int i = t; i < 64*128; i += 256) ws[i] = g_wt2[i];
    if (t < 64) { sc[t] = g_scale[1][t]; sh[t] = g_shift[1][t]; }
    __syncthreads();

    int row  = t & 127;
    int half = (t >> 7) * 64;
    const float4* xr = (const float4*)g_Y2 + (size_t)blockIdx.x * 2048 + row;
    ull acc2[32];
#pragma unroll
    for (int p = 0; p < 32; p++) acc2[p] = 0ull;

    float4 a0 = xr[0];
    float4 a1 = xr[128];
#pragma unroll 1
    for (int kc = 0; kc < 16; kc++) {
        float4 yv = a0; a0 = a1;
        a1 = xr[((kc < 14) ? (kc + 2) : 15) * 128];
        int kb = kc * 4;
        float ys[4] = {yv.x, yv.y, yv.z, yv.w};
#pragma unroll
        for (int kk = 0; kk < 4; kk++) {
            float xk = fmaxf(fmaf(ys[kk], sc[kb+kk], sh[kb+kk]), 0.f);
            ull xk2 = pk2(xk);
            const ulonglong2* wr = (const ulonglong2*)(ws + (kb+kk)*128 + half);
#pragma unroll
            for (int p = 0; p < 16; p++) {
                ulonglong2 wv = wr[p];
                fma2(acc2[2*p],   xk2, wv.x);
                fma2(acc2[2*p+1], xk2, wv.y);
            }
        }
    }

    __syncthreads();
#pragma unroll
    for (int p = 0; p < 32; p++) {
        float2 f = up2(acc2[p]);
        tile[row*129 + half + 2*p]     = f.x;
        tile[row*129 + half + 2*p + 1] = f.y;
    }
    __syncthreads();

    int c = t & 127, g = t >> 7;
    float sa = 0.f, qa = 0.f;
#pragma unroll 4
    for (int rr = g*64; rr < g*64 + 64; rr++) {
        float v = tile[rr*129 + c];
        sa += v; qa = fmaf(v, v, qa);
    }
    ps[g*128 + c] = sa; pq[g*128 + c] = qa;

#pragma unroll
    for (int e = t; e < 512; e += 256) {
        int qi = e >> 7, ch = e & 127;
        int r0 = qi * 32;
        float mx = tile[r0*129 + ch], mn = mx;
#pragma unroll 4
        for (int rr = r0 + 1; rr < r0 + 32; rr++) {
            float v = tile[rr*129 + ch];
            mx = fmaxf(mx, v); mn = fminf(mn, v);
        }
        g_Mx[(size_t)blockIdx.x*512 + e] = mx;
        g_Mn[(size_t)blockIdx.x*512 + e] = mn;
    }
    __syncthreads();
    if (t < 128) {
        g_psum[(size_t)t*4096 + blockIdx.x] = ps[t] + ps[128 + t];
        g_psq [(size_t)t*4096 + blockIdx.x] = pq[t] + pq[128 + t];
    }
}

// ------------- finalize BN stats: one block per channel, coalesced float4 reads ------------
__global__ __launch_bounds__(256)
void k_fin(const float* __restrict__ gma, const float* __restrict__ beta,
           int OC, int layer) {
    int c = blockIdx.x, t = threadIdx.x;
    const float4* Ps = (const float4*)(g_psum + (size_t)c * 4096);
    const float4* Pq = (const float4*)(g_psq  + (size_t)c * 4096);
    float s = 0.f, s2 = 0.f;
#pragma unroll
    for (int i = t; i < 1024; i += 256) {
        float4 a = Ps[i];
        float4 b = Pq[i];
        s  += a.x + a.y + a.z + a.w;
        s2 += b.x + b.y + b.z + b.w;
    }
#pragma unroll
    for (int off = 16; off; off >>= 1) {
        s  += __shfl_down_sync(0xffffffffu, s, off);
        s2 += __shfl_down_sync(0xffffffffu, s2, off);
    }
    __shared__ float a[8], a2[8];
    if ((t & 31) == 0) { a[t>>5] = s; a2[t>>5] = s2; }
    __syncthreads();
    if (t == 0) {
        double S = 0.0, S2 = 0.0;
#pragma unroll
        for (int wb = 0; wb < 8; wb++) { S += (double)a[wb]; S2 += (double)a2[wb]; }
        double inv  = 1.0 / (double)NROWS;
        double mean = S * inv;
        double var  = S2 * inv - mean * mean;
        float scale = (float)((double)gma[c] * rsqrt(var + 1e-5));
        float shift = (float)((double)beta[c] - mean * (double)scale);
        g_scale[layer][c] = scale;
        g_shift[layer][c] = shift;
    }
}

// ---------- pool: BN2 applied to raw min/max (monotone-exact) + transposed write -----------
__global__ __launch_bounds__(128)
void k_pool(float* __restrict__ out) {
    __shared__ float sm[128*33];
    int t = threadIdx.x;
    float sc = g_scale[2][t], sh = g_shift[2][t];
    int q0 = blockIdx.x * 32;
    int b  = q0 >> 10;
    const float* src = (sc > 0.f) ? g_Mx : g_Mn;
#pragma unroll 4
    for (int qi = 0; qi < 32; qi++) {
        float v = src[(size_t)(q0 + qi)*128 + t];
        sm[t*33 + qi] = fmaxf(fmaf(v, sc, sh), 0.f);
    }
    __syncthreads();
    int mloc = t & 31, og = t >> 5;
    int mg = q0 & 1023;
#pragma unroll
    for (int i = 0; i < 32; i++) {
        int oc = og + i*4;
        out[49152 + ((size_t)(b*128 + oc))*1024 + mg + mloc] = sm[oc*33 + mloc];
    }
}

// ------------------------- launch --------------------------------------------------------
extern "C" void kernel_launch(void* const* d_in, const int* in_sizes, int n_in,
                              void* d_out, int out_size) {
    const float* xyz = (const float*)d_in[0];
    const float* pts = (const float*)d_in[1];
    const float* w0  = (const float*)d_in[2];
    const float* g0  = (const float*)d_in[4];
    const float* be0 = (const float*)d_in[5];
    const float* w1  = (const float*)d_in[6];
    const float* g1  = (const float*)d_in[8];
    const float* be1 = (const float*)d_in[9];
    const float* w2  = (const float*)d_in[10];
    const float* g2  = (const float*)d_in[12];
    const float* be2 = (const float*)d_in[13];
    float* out = (float*)d_out;

    const int SMEM2 = 8704 * 4;    // 34816 B
    const int SMEM3 = 17152 * 4;   // 68608 B
    cudaFuncSetAttribute(k_gemm2, cudaFuncAttributeMaxDynamicSharedMemorySize, SMEM2);
    cudaFuncSetAttribute(k_gemm3, cudaFuncAttributeMaxDynamicSharedMemorySize, SMEM3);

    k_init<<<64, 256>>>(w0, w1, w2);
    k_front<<<208, 1024>>>(xyz, pts, out);
    k_knn<<<B_*NP_, 128>>>();

    k_gemm1<<<NROWS/128, 256>>>(xyz);
    k_fin<<<64, 256>>>(g0, be0, 64, 0);

    k_gemm2<<<NROWS/128, 128, SMEM2>>>();
    k_fin<<<64, 256>>>(g1, be1, 64, 1);

    k_gemm3<<<NROWS/128, 256, SMEM3>>>();
    k_fin<<<128, 256>>>(g2, be2, 128, 2);

    k_pool<<<B_*NP_/32, 128>>>(out);
}

// round 16
// speedup vs baseline: 1.0627x; 1.0140x over previous
#include <cuda_runtime.h>
#include <math_constants.h>

#define B_   16
#define N_   4096
#define NP_  1024
#define NS_  32
#define NROWS 524288   // B_*NP_*NS_

typedef unsigned long long ull;

// ------------------------- static device scratch (no allocation) -------------------------
__device__ __align__(16) float g_newxyz[B_*NP_*3];
__device__ __align__(16) float4 g_xyzw[B_*N_];       // (x,y,z,sq)
__device__ int   g_knn[B_*NP_*NS_];
__device__ __align__(16) float g_P [4194304];    // 65536 x 64   pts @ W0[3:]
__device__ __align__(16) float g_Y1[33554432];   // blocked 4096 x 16 x 128 x 4
__device__ __align__(16) float g_Y2[33554432];   // blocked 4096 x 16 x 128 x 4
__device__ __align__(16) float g_Mx[B_*NP_*128]; // raw per-(query,ch) max of layer-3 out
__device__ __align__(16) float g_Mn[B_*NP_*128]; // raw per-(query,ch) min
__device__ __align__(16) float g_psum[128*4096]; // channel-major: [c][bid]
__device__ __align__(16) float g_psq [128*4096];
__device__ float g_scale[3][128];
__device__ float g_shift[3][128];
__device__ __align__(16) float g_wt0[67*64];
__device__ __align__(16) float g_wt1[64*64];
__device__ __align__(16) float g_wt2[64*128];

// ------------------------- f32x2 packed helpers -------------------------
__device__ __forceinline__ void fma2(ull& d, ull a, ull b) {
    asm("fma.rn.f32x2 %0, %1, %2, %0;" : "+l"(d) : "l"(a), "l"(b));
}
__device__ __forceinline__ ull pk2(float x) {
    ull u;
    asm("mov.b64 %0, {%1, %2};" : "=l"(u) : "f"(x), "f"(x));
    return u;
}
__device__ __forceinline__ float2 up2(ull u) {
    float2 f;
    asm("mov.b64 {%0, %1}, %2;" : "=f"(f.x), "=f"(f.y) : "l"(u));
    return f;
}

// ------------------------- init (split in 3 so k_front is launch #4) ----------------------
__global__ void k_init0(const float* __restrict__ w0) {
    int t = blockIdx.x * blockDim.x + threadIdx.x;
    int stride = gridDim.x * blockDim.x;
    for (int l = t; l < 64*67; l += stride) { int oc = l / 67, k = l - oc*67; g_wt0[k*64 + oc] = w0[l]; }
}
__global__ void k_init1(const float* __restrict__ w1) {
    int t = blockIdx.x * blockDim.x + threadIdx.x;
    int stride = gridDim.x * blockDim.x;
    for (int l = t; l < 64*64; l += stride) { int oc = l >> 6, k = l & 63; g_wt1[k*64 + oc] = w1[l]; }
}
__global__ void k_init2(const float* __restrict__ w2) {
    int t = blockIdx.x * blockDim.x + threadIdx.x;
    int stride = gridDim.x * blockDim.x;
    for (int l = t; l < 128*64; l += stride){ int oc = l >> 6, k = l & 63; g_wt2[k*128 + oc] = w2[l]; }
}

// ------------------------- fused front: P precompute | xyzw table | FPS -------------------
__global__ __launch_bounds__(1024)
void k_front(const float* __restrict__ xyz, const float* __restrict__ pts,
             float* __restrict__ out) {
    __shared__ __align__(16) float ws[4096];
    __shared__ float sxyz[12288];
    __shared__ unsigned sv[2][32]; __shared__ int si_[2][32];
    int blk = blockIdx.x, t = threadIdx.x;

    if (blk < 128) {
        // ---- P = pts @ W0[3:,:]
        for (int i = t; i < 4096; i += 1024) ws[i] = g_wt0[192 + i];
        __syncthreads();
        int row  = blk * 512 + (t >> 1);
        int half = (t & 1) * 32;
        const float4* xr = (const float4*)(pts + (size_t)row * 64);
        ull acc2[16];
#pragma unroll
        for (int p = 0; p < 16; p++) acc2[p] = 0ull;
        float4 a0 = __ldg(&xr[0]);
        float4 a1 = __ldg(&xr[1]);
#pragma unroll 1
        for (int kc = 0; kc < 16; kc++) {
            float4 xv = a0; a0 = a1;
            a1 = __ldg(&xr[(kc < 14) ? (kc + 2) : 15]);
            float xs[4] = {xv.x, xv.y, xv.z, xv.w};
#pragma unroll
            for (int kk = 0; kk < 4; kk++) {
                ull xk2 = pk2(xs[kk]);
                const ulonglong2* wr = (const ulonglong2*)(ws + (kc*4 + kk)*64 + half);
#pragma unroll
                for (int p = 0; p < 8; p++) {
                    ulonglong2 wv = wr[p];
                    fma2(acc2[p*2],   xk2, wv.x);
                    fma2(acc2[p*2+1], xk2, wv.y);
                }
            }
        }
        ulonglong2* po = (ulonglong2*)(g_P + (size_t)row * 64 + half);
#pragma unroll
        for (int p = 0; p < 8; p++) po[p] = make_ulonglong2(acc2[2*p], acc2[2*p+1]);
        return;
    }
    if (blk < 192) {
        int n = (blk - 128) * 1024 + t;
        const float* X = xyz + (size_t)n * 3;
        float x = X[0], y = X[1], z = X[2];
        float sq = __fadd_rn(__fadd_rn(__fmul_rn(x,x), __fmul_rn(y,y)), __fmul_rn(z,z));
        g_xyzw[n] = make_float4(x, y, z, sq);
        return;
    }

    // ---- FPS: single barrier per iteration; centroid fetch from smem
    int b = blk - 192;
    int lane = t & 31, w = t >> 5;
    const float* X = xyz + (size_t)b * N_ * 3;
    float px[4], py[4], pz[4], dd[4];
#pragma unroll
    for (int j = 0; j < 4; j++) {
        int n = t*4 + j;
        px[j] = X[n*3]; py[j] = X[n*3+1]; pz[j] = X[n*3+2];
        dd[j] = 1e10f;
        sxyz[n*3]   = px[j];
        sxyz[n*3+1] = py[j];
        sxyz[n*3+2] = pz[j];
    }
    float ccx = X[0], ccy = X[1], ccz = X[2];
    float* nx = g_newxyz + (size_t)b * NP_ * 3;
    float* ox = out + (size_t)b * NP_ * 3;
    __syncthreads();

    for (int i = 0; i < NP_; i++) {
        if (t == 0) {
            nx[i*3] = ccx; nx[i*3+1] = ccy; nx[i*3+2] = ccz;
            ox[i*3] = ccx; ox[i*3+1] = ccy; ox[i*3+2] = ccz;
        }
        float bv = -1.0f; int bi = 0;
#pragma unroll
        for (int j = 0; j < 4; j++) {
            float dx = __fsub_rn(px[j], ccx);
            float dy = __fsub_rn(py[j], ccy);
            float dz = __fsub_rn(pz[j], ccz);
            float d  = __fadd_rn(__fadd_rn(__fmul_rn(dx,dx), __fmul_rn(dy,dy)), __fmul_rn(dz,dz));
            dd[j] = fminf(dd[j], d);
            if (dd[j] > bv) { bv = dd[j]; bi = t*4 + j; }
        }
        unsigned kv   = __float_as_uint(bv);
        unsigned vmax = __reduce_max_sync(0xffffffffu, kv);
        unsigned cand = (kv == vmax) ? (unsigned)bi : 0xffffffffu;
        unsigned imin = __reduce_min_sync(0xffffffffu, cand);
        int p = i & 1;
        if (lane == 0) { sv[p][w] = vmax; si_[p][w] = (int)imin; }
        __syncthreads();
        unsigned kv2 = sv[p][lane];
        int      ii  = si_[p][lane];
        unsigned vm2 = __reduce_max_sync(0xffffffffu, kv2);
        unsigned c2  = (kv2 == vm2) ? (unsigned)ii : 0xffffffffu;
        unsigned win = __reduce_min_sync(0xffffffffu, c2);
        ccx = sxyz[win*3]; ccy = sxyz[win*3+1]; ccz = sxyz[win*3+2];
    }
}

__device__ __forceinline__ unsigned fkey(float v) {
    unsigned u = __float_as_uint(v);
    return u ^ (unsigned)(((int)u >> 31) | 0x80000000);
}

// ------------------------- kNN: histogram radix-select (one block / query) -----------------
__global__ __launch_bounds__(128)
void k_knn() {
    int q = blockIdx.x, b = q >> 10, t = threadIdx.x;
    int lane = t & 31, w = t >> 5;
    const float4* X4 = g_xyzw + (size_t)b * N_;
    const float* Q = g_newxyz + (size_t)q * 3;
    float qx = Q[0], qy = Q[1], qz = Q[2];
    float sqn = __fadd_rn(__fadd_rn(__fmul_rn(qx,qx), __fmul_rn(qy,qy)), __fmul_rn(qz,qz));

    unsigned key[32];
#pragma unroll
    for (int i = 0; i < 32; i++) {
        float4 v = __ldg(&X4[i*128 + t]);
        float dot = __fadd_rn(__fadd_rn(__fmul_rn(qx,v.x), __fmul_rn(qy,v.y)), __fmul_rn(qz,v.z));
        float d2  = __fsub_rn(__fadd_rn(sqn, v.w), __fmul_rn(2.0f, dot));
        key[i] = fkey(d2);
    }

    __shared__ unsigned hist[2048];
    __shared__ unsigned sw[4];
    __shared__ unsigned spiv[3];
    __shared__ unsigned candk[64];
    __shared__ int candi[64];
    __shared__ int candn;

    for (int j = t; j < 2048; j += 128) hist[j] = 0;
    if (t == 0) candn = 0;
    __syncthreads();
#pragma unroll
    for (int i = 0; i < 32; i++) atomicAdd(&hist[key[i] >> 21], 1u);
    __syncthreads();
    unsigned s = 0;
#pragma unroll
    for (int j = 0; j < 16; j++) s += hist[t*16 + j];
    unsigned inc = s;
#pragma unroll
    for (int o = 1; o < 32; o <<= 1) { unsigned nn = __shfl_up_sync(~0u, inc, o); if (lane >= o) inc += nn; }
    if (lane == 31) sw[w] = inc;
    __syncthreads();
    unsigned wbase = 0;
    for (int j = 0; j < w; j++) wbase += sw[j];
    unsigned base = wbase + inc - s;
    if (base < 32 && base + s >= 32) {
        unsigned cum = base;
#pragma unroll
        for (int j = 0; j < 16; j++) {
            unsigned c = hist[t*16 + j];
            if (cum + c >= 32) { spiv[0] = t*16 + j; spiv[1] = cum; spiv[2] = c; break; }
            cum += c;
        }
    }
    __syncthreads();
    unsigned pb1 = spiv[0];
    unsigned cb  = spiv[1];
    unsigned pc  = spiv[2];
    unsigned Kstar, width;

    if (pc > 64) {
        unsigned need2 = 32 - cb;
        for (int j = t; j < 2048; j += 128) hist[j] = 0;
        __syncthreads();
#pragma unroll
        for (int i = 0; i < 32; i++)
            if ((key[i] >> 21) == pb1) atomicAdd(&hist[(key[i] >> 10) & 2047], 1u);
        __syncthreads();
        s = 0;
#pragma unroll
        for (int j = 0; j < 16; j++) s += hist[t*16 + j];
        inc = s;
#pragma unroll
        for (int o = 1; o < 32; o <<= 1) { unsigned nn = __shfl_up_sync(~0u, inc, o); if (lane >= o) inc += nn; }
        if (lane == 31) sw[w] = inc;
        __syncthreads();
        wbase = 0;
        for (int j = 0; j < w; j++) wbase += sw[j];
        base = wbase + inc - s;
        if (base < need2 && base + s >= need2) {
            unsigned cum = base;
#pragma unroll
            for (int j = 0; j < 16; j++) {
                unsigned c = hist[t*16 + j];
                if (cum + c >= need2) { spiv[0] = t*16 + j; spiv[1] = cum; break; }
                cum += c;
            }
        }
        __syncthreads();
        Kstar = (pb1 << 21) | (spiv[0] << 10);
        width = 1u << 10;
        cb = cb + spiv[1];
        __syncthreads();
    } else {
        Kstar = pb1 << 21;
        width = 1u << 21;
    }

    int ct = 0;
#pragma unroll
    for (int i = 0; i < 32; i++) ct += (key[i] < Kstar);
    int inci = ct;
#pragma unroll
    for (int o = 1; o < 32; o <<= 1) { int nn = __shfl_up_sync(~0u, inci, o); if (lane >= o) inci += nn; }
    if (lane == 31) sw[w] = (unsigned)inci;
    __syncthreads();
    int wb = 0;
    for (int j = 0; j < w; j++) wb += (int)sw[j];
    int slot = wb + inci - ct;
    int* KO = g_knn + (size_t)q * NS_;
#pragma unroll
    for (int i = 0; i < 32; i++) {
        unsigned k = key[i];
        if (k < Kstar) { KO[slot++] = i*128 + t; }
        else if (k - Kstar < width) {
            int p = atomicAdd(&candn, 1);
            if (p < 64) { candk[p] = k; candi[p] = i*128 + t; }
        }
    }
    __syncthreads();
    int L = candn; if (L > 64) L = 64;
    int need = 32 - (int)cb;
    if (t < L) {
        unsigned mk = candk[t]; int mi = candi[t];
        int rank = 0;
        for (int j = 0; j < L; j++) {
            unsigned kj = candk[j];
            rank += (kj < mk) || (kj == mk && candi[j] < mi);
        }
        if (rank < need) KO[cb + rank] = mi;
    }
}

// ---------- layer 1: gather(P) + rel_xyz @ W0[:3], half-row per thread (256 thr) -----------
__global__ __launch_bounds__(256)
void k_gemm1(const float* __restrict__ xyz) {
    __shared__ float ws[192];
    __shared__ float tile[64*65];
    __shared__ float ps[256], pq[256];
    int t = threadIdx.x;
    int row = t & 127, half = t >> 7;
    for (int i = t; i < 192; i += 256) ws[i] = g_wt0[i];
    __syncthreads();

    size_t r = (size_t)blockIdx.x * 128 + row;
    int b  = (int)(r >> 15);
    int bm = (int)(r >> 5);
    int j  = g_knn[r];
    const float* Pt = xyz + ((size_t)b * N_ + j) * 3;
    const float* Q  = g_newxyz + (size_t)bm * 3;
    float f0 = Pt[0] - Q[0], f1 = Pt[1] - Q[1], f2 = Pt[2] - Q[2];

    const float4* prow = (const float4*)(g_P + ((size_t)b * N_ + j) * 64) + half*8;
    float4 pv[8];
#pragma unroll
    for (int kc = 0; kc < 8; kc++) pv[kc] = __ldg(&prow[kc]);

    float acc[32];
    float4* yo = (float4*)g_Y1 + (size_t)blockIdx.x * 2048 + row;
#pragma unroll
    for (int kc = 0; kc < 8; kc++) {
        int o = half*32 + kc*4;
        float4 st;
        st.x = fmaf(f2, ws[128+o],   fmaf(f1, ws[64+o],   fmaf(f0, ws[o],   pv[kc].x)));
        st.y = fmaf(f2, ws[128+o+1], fmaf(f1, ws[64+o+1], fmaf(f0, ws[o+1], pv[kc].y)));
        st.z = fmaf(f2, ws[128+o+2], fmaf(f1, ws[64+o+2], fmaf(f0, ws[o+2], pv[kc].z)));
        st.w = fmaf(f2, ws[128+o+3], fmaf(f1, ws[64+o+3], fmaf(f0, ws[o+3], pv[kc].w)));
        yo[(half*8 + kc)*128] = st;
        acc[kc*4]   = st.x; acc[kc*4+1] = st.y;
        acc[kc*4+2] = st.z; acc[kc*4+3] = st.w;
    }

    float psa = 0.f, pqa = 0.f;
#pragma unroll
    for (int ph = 0; ph < 2; ph++) {
        if ((row >> 6) == ph) {
#pragma unroll
            for (int o = 0; o < 32; o++) tile[(row & 63)*65 + half*32 + o] = acc[o];
        }
        __syncthreads();
        int c = t & 63, g = t >> 6;
#pragma unroll 4
        for (int rr = g*16; rr < g*16 + 16; rr++) {
            float v = tile[rr*65 + c];
            psa += v; pqa = fmaf(v, v, pqa);
        }
        __syncthreads();
    }
    ps[t] = psa; pq[t] = pqa;
    __syncthreads();
    if (t < 64) {
        g_psum[(size_t)t*4096 + blockIdx.x] = ps[t] + ps[64+t] + ps[128+t] + ps[192+t];
        g_psq [(size_t)t*4096 + blockIdx.x] = pq[t] + pq[64+t] + pq[128+t] + pq[192+t];
    }
}

// ------------------------- layer 2: BN0+ReLU(Y1) @ W1 (f32x2, blocked, 128 thr) -----------
__global__ __launch_bounds__(128)
void k_gemm2() {
    extern __shared__ __align__(16) float dyn[];
    float* ws   = dyn;
    float* tile = dyn;
    float* sc   = dyn + 8320;
    float* sh   = sc + 64;
    float* ps   = sh + 64;
    float* pq   = ps + 128;
    int t = threadIdx.x;
    for (int i = t; i < 4096; i += 128) ws[i] = g_wt1[i];
    if (t < 64) { sc[t] = g_scale[0][t]; sh[t] = g_shift[0][t]; }
    __syncthreads();

    const float4* xr = (const float4*)g_Y1 + (size_t)blockIdx.x * 2048 + t;
    ull acc2[32];
#pragma unroll
    for (int p = 0; p < 32; p++) acc2[p] = 0ull;

    float4 a0 = xr[0];
    float4 a1 = xr[128];
#pragma unroll 1
    for (int kc = 0; kc < 16; kc++) {
        float4 yv = a0; a0 = a1;
        a1 = xr[((kc < 14) ? (kc + 2) : 15) * 128];
        int kb = kc * 4;
        float ys[4] = {yv.x, yv.y, yv.z, yv.w};
#pragma unroll
        for (int kk = 0; kk < 4; kk++) {
            float xk = fmaxf(fmaf(ys[kk], sc[kb+kk], sh[kb+kk]), 0.f);
            ull xk2 = pk2(xk);
            const ulonglong2* wr = (const ulonglong2*)(ws + (kb+kk)*64);
#pragma unroll
            for (int p = 0; p < 16; p++) {
                ulonglong2 wv = wr[p];
                fma2(acc2[2*p],   xk2, wv.x);
                fma2(acc2[2*p+1], xk2, wv.y);
            }
        }
    }
    ulonglong2* yo = (ulonglong2*)((float4*)g_Y2 + (size_t)blockIdx.x * 2048 + t);
#pragma unroll
    for (int kc = 0; kc < 16; kc++)
        yo[kc*128] = make_ulonglong2(acc2[2*kc], acc2[2*kc+1]);

    __syncthreads();
#pragma unroll
    for (int p = 0; p < 32; p++) {
        float2 f = up2(acc2[p]);
        tile[t*65 + 2*p]     = f.x;
        tile[t*65 + 2*p + 1] = f.y;
    }
    __syncthreads();
    int c = t & 63, g = t >> 6;
    float sa = 0.f, qa = 0.f;
#pragma unroll 4
    for (int rr = g*64; rr < g*64 + 64; rr++) {
        float v = tile[rr*65 + c];
        sa += v; qa = fmaf(v, v, qa);
    }
    ps[g*64 + c] = sa; pq[g*64 + c] = qa;
    __syncthreads();
    if (t < 64) {
        g_psum[(size_t)t*4096 + blockIdx.x] = ps[t] + ps[64 + t];
        g_psq [(size_t)t*4096 + blockIdx.x] = pq[t] + pq[64 + t];
    }
}

// --------- layer 3: BN1+ReLU(Y2) @ W2 -> 128 ch; NO Y3 store, per-query raw min/max --------
__global__ __launch_bounds__(256)
void k_gemm3() {
    extern __shared__ __align__(16) float dyn[];
    float* ws   = dyn;
    float* tile = dyn;
    float* sc   = dyn + 16512;
    float* sh   = sc + 64;
    float* ps   = sh + 64;
    float* pq   = ps + 256;
    int t = threadIdx.x;
    for (int i = t; i < 64*128; i += 256) ws[i] = g_wt2[i];
    if (t < 64) { sc[t] = g_scale[1][t]; sh[t] = g_shift[1][t]; }
    __syncthreads();

    int row  = t & 127;
    int half = (t >> 7) * 64;
    const float4* xr = (const float4*)g_Y2 + (size_t)blockIdx.x * 2048 + row;
    ull acc2[32];
#pragma unroll
    for (int p = 0; p < 32; p++) acc2[p] = 0ull;

    float4 a0 = xr[0];
    float4 a1 = xr[128];
#pragma unroll 1
    for (int kc = 0; kc < 16; kc++) {
        float4 yv = a0; a0 = a1;
        a1 = xr[((kc < 14) ? (kc + 2) : 15) * 128];
        int kb = kc * 4;
        float ys[4] = {yv.x, yv.y, yv.z, yv.w};
#pragma unroll
        for (int kk = 0; kk < 4; kk++) {
            float xk = fmaxf(fmaf(ys[kk], sc[kb+kk], sh[kb+kk]), 0.f);
            ull xk2 = pk2(xk);
            const ulonglong2* wr = (const ulonglong2*)(ws + (kb+kk)*128 + half);
#pragma unroll
            for (int p = 0; p < 16; p++) {
                ulonglong2 wv = wr[p];
                fma2(acc2[2*p],   xk2, wv.x);
                fma2(acc2[2*p+1], xk2, wv.y);
            }
        }
    }

    __syncthreads();
#pragma unroll
    for (int p = 0; p < 32; p++) {
        float2 f = up2(acc2[p]);
        tile[row*129 + half + 2*p]     = f.x;
        tile[row*129 + half + 2*p + 1] = f.y;
    }
    __syncthreads();

    int c = t & 127, g = t >> 7;
    float sa = 0.f, qa = 0.f;
#pragma unroll 4
    for (int rr = g*64; rr < g*64 + 64; rr++) {
        float v = tile[rr*129 + c];
        sa += v; qa = fmaf(v, v, qa);
    }
    ps[g*128 + c] = sa; pq[g*128 + c] = qa;

#pragma unroll
    for (int e = t; e < 512; e += 256) {
        int qi = e >> 7, ch = e & 127;
        int r0 = qi * 32;
        float mx = tile[r0*129 + ch], mn = mx;
#pragma unroll 4
        for (int rr = r0 + 1; rr < r0 + 32; rr++) {
            float v = tile[rr*129 + ch];
            mx = fmaxf(mx, v); mn = fminf(mn, v);
        }
        g_Mx[(size_t)blockIdx.x*512 + e] = mx;
        g_Mn[(size_t)blockIdx.x*512 + e] = mn;
    }
    __syncthreads();
    if (t < 128) {
        g_psum[(size_t)t*4096 + blockIdx.x] = ps[t] + ps[128 + t];
        g_psq [(size_t)t*4096 + blockIdx.x] = pq[t] + pq[128 + t];
    }
}

// ------------- finalize BN stats: one block per channel, coalesced float4 reads ------------
__global__ __launch_bounds__(256)
void k_fin(const float* __restrict__ gma, const float* __restrict__ beta,
           int OC, int layer) {
    int c = blockIdx.x, t = threadIdx.x;
    const float4* Ps = (const float4*)(g_psum + (size_t)c * 4096);
    const float4* Pq = (const float4*)(g_psq  + (size_t)c * 4096);
    float s = 0.f, s2 = 0.f;
#pragma unroll
    for (int i = t; i < 1024; i += 256) {
        float4 a = Ps[i];
        float4 b = Pq[i];
        s  += a.x + a.y + a.z + a.w;
        s2 += b.x + b.y + b.z + b.w;
    }
#pragma unroll
    for (int off = 16; off; off >>= 1) {
        s  += __shfl_down_sync(0xffffffffu, s, off);
        s2 += __shfl_down_sync(0xffffffffu, s2, off);
    }
    __shared__ float a[8], a2[8];
    if ((t & 31) == 0) { a[t>>5] = s; a2[t>>5] = s2; }
    __syncthreads();
    if (t == 0) {
        double S = 0.0, S2 = 0.0;
#pragma unroll
        for (int wb = 0; wb < 8; wb++) { S += (double)a[wb]; S2 += (double)a2[wb]; }
        double inv  = 1.0 / (double)NROWS;
        double mean = S * inv;
        double var  = S2 * inv - mean * mean;
        float scale = (float)((double)gma[c] * rsqrt(var + 1e-5));
        float shift = (float)((double)beta[c] - mean * (double)scale);
        g_scale[layer][c] = scale;
        g_shift[layer][c] = shift;
    }
}

// ---------- pool: BN2 applied to raw min/max (monotone-exact) + transposed write -----------
__global__ __launch_bounds__(128)
void k_pool(float* __restrict__ out) {
    __shared__ float sm[128*33];
    int t = threadIdx.x;
    float sc = g_scale[2][t], sh = g_shift[2][t];
    int q0 = blockIdx.x * 32;
    int b  = q0 >> 10;
    const float* src = (sc > 0.f) ? g_Mx : g_Mn;
#pragma unroll 4
    for (int qi = 0; qi < 32; qi++) {
        float v = src[(size_t)(q0 + qi)*128 + t];
        sm[t*33 + qi] = fmaxf(fmaf(v, sc, sh), 0.f);
    }
    __syncthreads();
    int mloc = t & 31, og = t >> 5;
    int mg = q0 & 1023;
#pragma unroll
    for (int i = 0; i < 32; i++) {
        int oc = og + i*4;
        out[49152 + ((size_t)(b*128 + oc))*1024 + mg + mloc] = sm[oc*33 + mloc];
    }
}

// ------------------------- launch --------------------------------------------------------
extern "C" void kernel_launch(void* const* d_in, const int* in_sizes, int n_in,
                              void* d_out, int out_size) {
    const float* xyz = (const float*)d_in[0];
    const float* pts = (const float*)d_in[1];
    const float* w0  = (const float*)d_in[2];
    const float* g0  = (const float*)d_in[4];
    const float* be0 = (const float*)d_in[5];
    const float* w1  = (const float*)d_in[6];
    const float* g1  = (const float*)d_in[8];
    const float* be1 = (const float*)d_in[9];
    const float* w2  = (const float*)d_in[10];
    const float* g2  = (const float*)d_in[12];
    const float* be2 = (const float*)d_in[13];
    float* out = (float*)d_out;

    const int SMEM2 = 8704 * 4;    // 34816 B
    const int SMEM3 = 17152 * 4;   // 68608 B
    cudaFuncSetAttribute(k_gemm2, cudaFuncAttributeMaxDynamicSharedMemorySize, SMEM2);
    cudaFuncSetAttribute(k_gemm3, cudaFuncAttributeMaxDynamicSharedMemorySize, SMEM3);

    k_init0<<<32, 256>>>(w0);
    k_init1<<<32, 256>>>(w1);
    k_init2<<<32, 256>>>(w2);
    k_front<<<208, 1024>>>(xyz, pts, out);   // <- launch #4: profiled
    k_knn<<<B_*NP_, 128>>>();

    k_gemm1<<<NROWS/128, 256>>>(xyz);
    k_fin<<<64, 256>>>(g0, be0, 64, 0);

    k_gemm2<<<NROWS/128, 128, SMEM2>>>();
    k_fin<<<64, 256>>>(g1, be1, 64, 1);

    k_gemm3<<<NROWS/128, 256, SMEM3>>>();
    k_fin<<<128, 256>>>(g2, be2, 128, 2);

    k_pool<<<B_*NP_/32, 128>>>(out);
}

// round 17
// speedup vs baseline: 1.1647x; 1.0960x over previous
#include <cuda_runtime.h>
#include <math_constants.h>

#define B_   16
#define N_   4096
#define NP_  1024
#define NS_  32
#define NROWS 524288   // B_*NP_*NS_

typedef unsigned long long ull;

// ------------------------- static device scratch (no allocation) -------------------------
__device__ __align__(16) float g_newxyz[B_*NP_*3];
__device__ __align__(16) float4 g_xyzw[B_*N_];       // (x,y,z,sq)
__device__ int   g_knn[B_*NP_*NS_];
__device__ __align__(16) float g_P [4194304];    // 65536 x 64   pts @ W0[3:]
__device__ __align__(16) float g_Y1[33554432];   // blocked 4096 x 16 x 128 x 4
__device__ __align__(16) float g_Y2[33554432];   // blocked 4096 x 16 x 128 x 4
__device__ __align__(16) float g_Mx[B_*NP_*128]; // raw per-(query,ch) max of layer-3 out
__device__ __align__(16) float g_Mn[B_*NP_*128]; // raw per-(query,ch) min
__device__ __align__(16) float g_psum[128*4096]; // channel-major: [c][bid]
__device__ __align__(16) float g_psq [128*4096];
__device__ float g_scale[3][128];
__device__ float g_shift[3][128];
__device__ __align__(16) float g_wt0[67*64];
__device__ __align__(16) float g_wt1[64*64];
__device__ __align__(16) float g_wt2[64*128];

// ------------------------- f32x2 packed helpers -------------------------
__device__ __forceinline__ void fma2(ull& d, ull a, ull b) {
    asm("fma.rn.f32x2 %0, %1, %2, %0;" : "+l"(d) : "l"(a), "l"(b));
}
__device__ __forceinline__ ull add2(ull a, ull b) {
    ull d; asm("add.rn.f32x2 %0, %1, %2;" : "=l"(d) : "l"(a), "l"(b)); return d;
}
__device__ __forceinline__ ull mul2(ull a, ull b) {
    ull d; asm("mul.rn.f32x2 %0, %1, %2;" : "=l"(d) : "l"(a), "l"(b)); return d;
}
__device__ __forceinline__ ull pk2(float x) {
    ull u;
    asm("mov.b64 %0, {%1, %2};" : "=l"(u) : "f"(x), "f"(x));
    return u;
}
__device__ __forceinline__ ull pk2f(float lo, float hi) {
    ull u;
    asm("mov.b64 %0, {%1, %2};" : "=l"(u) : "f"(lo), "f"(hi));
    return u;
}
__device__ __forceinline__ float2 up2(ull u) {
    float2 f;
    asm("mov.b64 {%0, %1}, %2;" : "=f"(f.x), "=f"(f.y) : "l"(u));
    return f;
}

// ------------------------- init (split in 3 so k_front is launch #4) ----------------------
__global__ void k_init0(const float* __restrict__ w0) {
    int t = blockIdx.x * blockDim.x + threadIdx.x;
    int stride = gridDim.x * blockDim.x;
    for (int l = t; l < 64*67; l += stride) { int oc = l / 67, k = l - oc*67; g_wt0[k*64 + oc] = w0[l]; }
}
__global__ void k_init1(const float* __restrict__ w1) {
    int t = blockIdx.x * blockDim.x + threadIdx.x;
    int stride = gridDim.x * blockDim.x;
    for (int l = t; l < 64*64; l += stride) { int oc = l >> 6, k = l & 63; g_wt1[k*64 + oc] = w1[l]; }
}
__global__ void k_init2(const float* __restrict__ w2) {
    int t = blockIdx.x * blockDim.x + threadIdx.x;
    int stride = gridDim.x * blockDim.x;
    for (int l = t; l < 128*64; l += stride){ int oc = l >> 6, k = l & 63; g_wt2[k*128 + oc] = w2[l]; }
}

// ------------------------- fused front: P precompute | xyzw table | FPS -------------------
__global__ __launch_bounds__(1024)
void k_front(const float* __restrict__ xyz, const float* __restrict__ pts,
             float* __restrict__ out) {
    __shared__ __align__(16) float ws[4096];
    __shared__ float sxyz[12288];
    __shared__ unsigned sv[2][32]; __shared__ int si_[2][32];
    int blk = blockIdx.x, t = threadIdx.x;

    if (blk < 128) {
        // ---- P = pts @ W0[3:,:]
        for (int i = t; i < 4096; i += 1024) ws[i] = g_wt0[192 + i];
        __syncthreads();
        int row  = blk * 512 + (t >> 1);
        int half = (t & 1) * 32;
        const float4* xr = (const float4*)(pts + (size_t)row * 64);
        ull acc2[16];
#pragma unroll
        for (int p = 0; p < 16; p++) acc2[p] = 0ull;
        float4 a0 = __ldg(&xr[0]);
        float4 a1 = __ldg(&xr[1]);
#pragma unroll 1
        for (int kc = 0; kc < 16; kc++) {
            float4 xv = a0; a0 = a1;
            a1 = __ldg(&xr[(kc < 14) ? (kc + 2) : 15]);
            float xs[4] = {xv.x, xv.y, xv.z, xv.w};
#pragma unroll
            for (int kk = 0; kk < 4; kk++) {
                ull xk2 = pk2(xs[kk]);
                const ulonglong2* wr = (const ulonglong2*)(ws + (kc*4 + kk)*64 + half);
#pragma unroll
                for (int p = 0; p < 8; p++) {
                    ulonglong2 wv = wr[p];
                    fma2(acc2[p*2],   xk2, wv.x);
                    fma2(acc2[p*2+1], xk2, wv.y);
                }
            }
        }
        ulonglong2* po = (ulonglong2*)(g_P + (size_t)row * 64 + half);
#pragma unroll
        for (int p = 0; p < 8; p++) po[p] = make_ulonglong2(acc2[2*p], acc2[2*p+1]);
        return;
    }
    if (blk < 192) {
        int n = (blk - 128) * 1024 + t;
        const float* X = xyz + (size_t)n * 3;
        float x = X[0], y = X[1], z = X[2];
        float sq = __fadd_rn(__fadd_rn(__fmul_rn(x,x), __fmul_rn(y,y)), __fmul_rn(z,z));
        g_xyzw[n] = make_float4(x, y, z, sq);
        return;
    }

    // ---- FPS: packed f32x2 distance chain (bitwise == scalar), 1 barrier/iter
    int b = blk - 192;
    int lane = t & 31, w = t >> 5;
    const float* X = xyz + (size_t)b * N_ * 3;
    ull px2[2], py2[2], pz2[2];
    float dd[4];
    {
        float lx[4], ly[4], lz[4];
#pragma unroll
        for (int j = 0; j < 4; j++) {
            int n = t*4 + j;
            lx[j] = X[n*3]; ly[j] = X[n*3+1]; lz[j] = X[n*3+2];
            dd[j] = 1e10f;
            sxyz[n*3]   = lx[j];
            sxyz[n*3+1] = ly[j];
            sxyz[n*3+2] = lz[j];
        }
        px2[0] = pk2f(lx[0], lx[1]); px2[1] = pk2f(lx[2], lx[3]);
        py2[0] = pk2f(ly[0], ly[1]); py2[1] = pk2f(ly[2], ly[3]);
        pz2[0] = pk2f(lz[0], lz[1]); pz2[1] = pk2f(lz[2], lz[3]);
    }
    float ccx = X[0], ccy = X[1], ccz = X[2];
    float* nx = g_newxyz + (size_t)b * NP_ * 3;
    float* ox = out + (size_t)b * NP_ * 3;
    __syncthreads();

    for (int i = 0; i < NP_; i++) {
        if (t == 0) {
            nx[i*3] = ccx; nx[i*3+1] = ccy; nx[i*3+2] = ccz;
            ox[i*3] = ccx; ox[i*3+1] = ccy; ox[i*3+2] = ccz;
        }
        // IEEE: a - b == a + (-b); negation exact -> chain bitwise == scalar version
        ull ncx = pk2(-ccx), ncy = pk2(-ccy), ncz = pk2(-ccz);
        float bv = -1.0f; int bi = 0;
#pragma unroll
        for (int jp = 0; jp < 2; jp++) {
            ull dx = add2(px2[jp], ncx);
            ull dy = add2(py2[jp], ncy);
            ull dz = add2(pz2[jp], ncz);
            ull xx = mul2(dx, dx);
            ull yy = mul2(dy, dy);
            ull zz = mul2(dz, dz);
            ull d2 = add2(add2(xx, yy), zz);
            float2 dn = up2(d2);
            int j0 = jp*2, j1 = jp*2 + 1;
            dd[j0] = fminf(dd[j0], dn.x);
            dd[j1] = fminf(dd[j1], dn.y);
            if (dd[j0] > bv) { bv = dd[j0]; bi = t*4 + j0; }
            if (dd[j1] > bv) { bv = dd[j1]; bi = t*4 + j1; }
        }
        unsigned kv   = __float_as_uint(bv);
        unsigned vmax = __reduce_max_sync(0xffffffffu, kv);
        unsigned cand = (kv == vmax) ? (unsigned)bi : 0xffffffffu;
        unsigned imin = __reduce_min_sync(0xffffffffu, cand);
        int p = i & 1;
        if (lane == 0) { sv[p][w] = vmax; si_[p][w] = (int)imin; }
        __syncthreads();
        unsigned kv2 = sv[p][lane];
        int      ii  = si_[p][lane];
        unsigned vm2 = __reduce_max_sync(0xffffffffu, kv2);
        unsigned c2  = (kv2 == vm2) ? (unsigned)ii : 0xffffffffu;
        unsigned win = __reduce_min_sync(0xffffffffu, c2);
        ccx = sxyz[win*3]; ccy = sxyz[win*3+1]; ccz = sxyz[win*3+2];
    }
}

__device__ __forceinline__ unsigned fkey(float v) {
    unsigned u = __float_as_uint(v);
    return u ^ (unsigned)(((int)u >> 31) | 0x80000000);
}

// ------------------------- kNN: histogram radix-select (one block / query) -----------------
__global__ __launch_bounds__(128)
void k_knn() {
    int q = blockIdx.x, b = q >> 10, t = threadIdx.x;
    int lane = t & 31, w = t >> 5;
    const float4* X4 = g_xyzw + (size_t)b * N_;
    const float* Q = g_newxyz + (size_t)q * 3;
    float qx = Q[0], qy = Q[1], qz = Q[2];
    float sqn = __fadd_rn(__fadd_rn(__fmul_rn(qx,qx), __fmul_rn(qy,qy)), __fmul_rn(qz,qz));

    unsigned key[32];
#pragma unroll
    for (int i = 0; i < 32; i++) {
        float4 v = __ldg(&X4[i*128 + t]);
        float dot = __fadd_rn(__fadd_rn(__fmul_rn(qx,v.x), __fmul_rn(qy,v.y)), __fmul_rn(qz,v.z));
        float d2  = __fsub_rn(__fadd_rn(sqn, v.w), __fmul_rn(2.0f, dot));
        key[i] = fkey(d2);
    }

    __shared__ unsigned hist[2048];
    __shared__ unsigned sw[4];
    __shared__ unsigned spiv[3];
    __shared__ unsigned candk[64];
    __shared__ int candi[64];
    __shared__ int candn;

    for (int j = t; j < 2048; j += 128) hist[j] = 0;
    if (t == 0) candn = 0;
    __syncthreads();
#pragma unroll
    for (int i = 0; i < 32; i++) atomicAdd(&hist[key[i] >> 21], 1u);
    __syncthreads();
    unsigned s = 0;
#pragma unroll
    for (int j = 0; j < 16; j++) s += hist[t*16 + j];
    unsigned inc = s;
#pragma unroll
    for (int o = 1; o < 32; o <<= 1) { unsigned nn = __shfl_up_sync(~0u, inc, o); if (lane >= o) inc += nn; }
    if (lane == 31) sw[w] = inc;
    __syncthreads();
    unsigned wbase = 0;
    for (int j = 0; j < w; j++) wbase += sw[j];
    unsigned base = wbase + inc - s;
    if (base < 32 && base + s >= 32) {
        unsigned cum = base;
#pragma unroll
        for (int j = 0; j < 16; j++) {
            unsigned c = hist[t*16 + j];
            if (cum + c >= 32) { spiv[0] = t*16 + j; spiv[1] = cum; spiv[2] = c; break; }
            cum += c;
        }
    }
    __syncthreads();
    unsigned pb1 = spiv[0];
    unsigned cb  = spiv[1];
    unsigned pc  = spiv[2];
    unsigned Kstar, width;

    if (pc > 64) {
        unsigned need2 = 32 - cb;
        for (int j = t; j < 2048; j += 128) hist[j] = 0;
        __syncthreads();
#pragma unroll
        for (int i = 0; i < 32; i++)
            if ((key[i] >> 21) == pb1) atomicAdd(&hist[(key[i] >> 10) & 2047], 1u);
        __syncthreads();
        s = 0;
#pragma unroll
        for (int j = 0; j < 16; j++) s += hist[t*16 + j];
        inc = s;
#pragma unroll
        for (int o = 1; o < 32; o <<= 1) { unsigned nn = __shfl_up_sync(~0u, inc, o); if (lane >= o) inc += nn; }
        if (lane == 31) sw[w] = inc;
        __syncthreads();
        wbase = 0;
        for (int j = 0; j < w; j++) wbase += sw[j];
        base = wbase + inc - s;
        if (base < need2 && base + s >= need2) {
            unsigned cum = base;
#pragma unroll
            for (int j = 0; j < 16; j++) {
                unsigned c = hist[t*16 + j];
                if (cum + c >= need2) { spiv[0] = t*16 + j; spiv[1] = cum; break; }
                cum += c;
            }
        }
        __syncthreads();
        Kstar = (pb1 << 21) | (spiv[0] << 10);
        width = 1u << 10;
        cb = cb + spiv[1];
        __syncthreads();
    } else {
        Kstar = pb1 << 21;
        width = 1u << 21;
    }

    int ct = 0;
#pragma unroll
    for (int i = 0; i < 32; i++) ct += (key[i] < Kstar);
    int inci = ct;
#pragma unroll
    for (int o = 1; o < 32; o <<= 1) { int nn = __shfl_up_sync(~0u, inci, o); if (lane >= o) inci += nn; }
    if (lane == 31) sw[w] = (unsigned)inci;
    __syncthreads();
    int wb = 0;
    for (int j = 0; j < w; j++) wb += (int)sw[j];
    int slot = wb + inci - ct;
    int* KO = g_knn + (size_t)q * NS_;
#pragma unroll
    for (int i = 0; i < 32; i++) {
        unsigned k = key[i];
        if (k < Kstar) { KO[slot++] = i*128 + t; }
        else if (k - Kstar < width) {
            int p = atomicAdd(&candn, 1);
            if (p < 64) { candk[p] = k; candi[p] = i*128 + t; }
        }
    }
    __syncthreads();
    int L = candn; if (L > 64) L = 64;
    int need = 32 - (int)cb;
    if (t < L) {
        unsigned mk = candk[t]; int mi = candi[t];
        int rank = 0;
        for (int j = 0; j < L; j++) {
            unsigned kj = candk[j];
            rank += (kj < mk) || (kj == mk && candi[j] < mi);
        }
        if (rank < need) KO[cb + rank] = mi;
    }
}

// ---------- layer 1: gather(P) + rel_xyz @ W0[:3], half-row per thread (256 thr) -----------
__global__ __launch_bounds__(256)
void k_gemm1(const float* __restrict__ xyz) {
    __shared__ float ws[192];
    __shared__ float tile[64*65];
    __shared__ float ps[256], pq[256];
    int t = threadIdx.x;
    int row = t & 127, half = t >> 7;
    for (int i = t; i < 192; i += 256) ws[i] = g_wt0[i];
    __syncthreads();

    size_t r = (size_t)blockIdx.x * 128 + row;
    int b  = (int)(r >> 15);
    int bm = (int)(r >> 5);
    int j  = g_knn[r];
    const float* Pt = xyz + ((size_t)b * N_ + j) * 3;
    const float* Q  = g_newxyz + (size_t)bm * 3;
    float f0 = Pt[0] - Q[0], f1 = Pt[1] - Q[1], f2 = Pt[2] - Q[2];

    const float4* prow = (const float4*)(g_P + ((size_t)b * N_ + j) * 64) + half*8;
    float4 pv[8];
#pragma unroll
    for (int kc = 0; kc < 8; kc++) pv[kc] = __ldg(&prow[kc]);

    float acc[32];
    float4* yo = (float4*)g_Y1 + (size_t)blockIdx.x * 2048 + row;
#pragma unroll
    for (int kc = 0; kc < 8; kc++) {
        int o = half*32 + kc*4;
        float4 st;
        st.x = fmaf(f2, ws[128+o],   fmaf(f1, ws[64+o],   fmaf(f0, ws[o],   pv[kc].x)));
        st.y = fmaf(f2, ws[128+o+1], fmaf(f1, ws[64+o+1], fmaf(f0, ws[o+1], pv[kc].y)));
        st.z = fmaf(f2, ws[128+o+2], fmaf(f1, ws[64+o+2], fmaf(f0, ws[o+2], pv[kc].z)));
        st.w = fmaf(f2, ws[128+o+3], fmaf(f1, ws[64+o+3], fmaf(f0, ws[o+3], pv[kc].w)));
        yo[(half*8 + kc)*128] = st;
        acc[kc*4]   = st.x; acc[kc*4+1] = st.y;
        acc[kc*4+2] = st.z; acc[kc*4+3] = st.w;
    }

    float psa = 0.f, pqa = 0.f;
#pragma unroll
    for (int ph = 0; ph < 2; ph++) {
        if ((row >> 6) == ph) {
#pragma unroll
            for (int o = 0; o < 32; o++) tile[(row & 63)*65 + half*32 + o] = acc[o];
        }
        __syncthreads();
        int c = t & 63, g = t >> 6;
#pragma unroll 4
        for (int rr = g*16; rr < g*16 + 16; rr++) {
            float v = tile[rr*65 + c];
            psa += v; pqa = fmaf(v, v, pqa);
        }
        __syncthreads();
    }
    ps[t] = psa; pq[t] = pqa;
    __syncthreads();
    if (t < 64) {
        g_psum[(size_t)t*4096 + blockIdx.x] = ps[t] + ps[64+t] + ps[128+t] + ps[192+t];
        g_psq [(size_t)t*4096 + blockIdx.x] = pq[t] + pq[64+t] + pq[128+t] + pq[192+t];
    }
}

// ------------------------- layer 2: BN0+ReLU(Y1) @ W1 (f32x2, blocked, 128 thr) -----------
__global__ __launch_bounds__(128)
void k_gemm2() {
    extern __shared__ __align__(16) float dyn[];
    float* ws   = dyn;
    float* tile = dyn;
    float* sc   = dyn + 8320;
    float* sh   = sc + 64;
    float* ps   = sh + 64;
    float* pq   = ps + 128;
    int t = threadIdx.x;
    for (int i = t; i < 4096; i += 128) ws[i] = g_wt1[i];
    if (t < 64) { sc[t] = g_scale[0][t]; sh[t] = g_shift[0][t]; }
    __syncthreads();

    const float4* xr = (const float4*)g_Y1 + (size_t)blockIdx.x * 2048 + t;
    ull acc2[32];
#pragma unroll
    for (int p = 0; p < 32; p++) acc2[p] = 0ull;

    float4 a0 = xr[0];
    float4 a1 = xr[128];
#pragma unroll 1
    for (int kc = 0; kc < 16; kc++) {
        float4 yv = a0; a0 = a1;
        a1 = xr[((kc < 14) ? (kc + 2) : 15) * 128];
        int kb = kc * 4;
        float ys[4] = {yv.x, yv.y, yv.z, yv.w};
#pragma unroll
        for (int kk = 0; kk < 4; kk++) {
            float xk = fmaxf(fmaf(ys[kk], sc[kb+kk], sh[kb+kk]), 0.f);
            ull xk2 = pk2(xk);
            const ulonglong2* wr = (const ulonglong2*)(ws + (kb+kk)*64);
#pragma unroll
            for (int p = 0; p < 16; p++) {
                ulonglong2 wv = wr[p];
                fma2(acc2[2*p],   xk2, wv.x);
                fma2(acc2[2*p+1], xk2, wv.y);
            }
        }
    }
    ulonglong2* yo = (ulonglong2*)((float4*)g_Y2 + (size_t)blockIdx.x * 2048 + t);
#pragma unroll
    for (int kc = 0; kc < 16; kc++)
        yo[kc*128] = make_ulonglong2(acc2[2*kc], acc2[2*kc+1]);

    __syncthreads();
#pragma unroll
    for (int p = 0; p < 32; p++) {
        float2 f = up2(acc2[p]);
        tile[t*65 + 2*p]     = f.x;
        tile[t*65 + 2*p + 1] = f.y;
    }
    __syncthreads();
    int c = t & 63, g = t >> 6;
    float sa = 0.f, qa = 0.f;
#pragma unroll 4
    for (int rr = g*64; rr < g*64 + 64; rr++) {
        float v = tile[rr*65 + c];
        sa += v; qa = fmaf(v, v, qa);
    }
    ps[g*64 + c] = sa; pq[g*64 + c] = qa;
    __syncthreads();
    if (t < 64) {
        g_psum[(size_t)t*4096 + blockIdx.x] = ps[t] + ps[64 + t];
        g_psq [(size_t)t*4096 + blockIdx.x] = pq[t] + pq[64 + t];
    }
}

// --------- layer 3: BN1+ReLU(Y2) @ W2 -> 128 ch; NO Y3 store, per-query raw min/max --------
__global__ __launch_bounds__(256)
void k_gemm3() {
    extern __shared__ __align__(16) float dyn[];
    float* ws   = dyn;
    float* tile = dyn;
    float* sc   = dyn + 16512;
    float* sh   = sc + 64;
    float* ps   = sh + 64;
    float* pq   = ps + 256;
    int t = threadIdx.x;
    for (int i = t; i < 64*128; i += 256) ws[i] = g_wt2[i];
    if (t < 64) { sc[t] = g_scale[1][t]; sh[t] = g_shift[1][t]; }
    __syncthreads();

    int row  = t & 127;
    int half = (t >> 7) * 64;
    const float4* xr = (const float4*)g_Y2 + (size_t)blockIdx.x * 2048 + row;
    ull acc2[32];
#pragma unroll
    for (int p = 0; p < 32; p++) acc2[p] = 0ull;

    float4 a0 = xr[0];
    float4 a1 = xr[128];
#pragma unroll 1
    for (int kc = 0; kc < 16; kc++) {
        float4 yv = a0; a0 = a1;
        a1 = xr[((kc < 14) ? (kc + 2) : 15) * 128];
        int kb = kc * 4;
        float ys[4] = {yv.x, yv.y, yv.z, yv.w};
#pragma unroll
        for (int kk = 0; kk < 4; kk++) {
            float xk = fmaxf(fmaf(ys[kk], sc[kb+kk], sh[kb+kk]), 0.f);
            ull xk2 = pk2(xk);
            const ulonglong2* wr = (const ulonglong2*)(ws + (kb+kk)*128 + half);
#pragma unroll
            for (int p = 0; p < 16; p++) {
                ulonglong2 wv = wr[p];
                fma2(acc2[2*p],   xk2, wv.x);
                fma2(acc2[2*p+1], xk2, wv.y);
            }
        }
    }

    __syncthreads();
#pragma unroll
    for (int p = 0; p < 32; p++) {
        float2 f = up2(acc2[p]);
        tile[row*129 + half + 2*p]     = f.x;
        tile[row*129 + half + 2*p + 1] = f.y;
    }
    __syncthreads();

    int c = t & 127, g = t >> 7;
    float sa = 0.f, qa = 0.f;
#pragma unroll 4
    for (int rr = g*64; rr < g*64 + 64; rr++) {
        float v = tile[rr*129 + c];
        sa += v; qa = fmaf(v, v, qa);
    }
    ps[g*128 + c] = sa; pq[g*128 + c] = qa;

#pragma unroll
    for (int e = t; e < 512; e += 256) {
        int qi = e >> 7, ch = e & 127;
        int r0 = qi * 32;
        float mx = tile[r0*129 + ch], mn = mx;
#pragma unroll 4
        for (int rr = r0 + 1; rr < r0 + 32; rr++) {
            float v = tile[rr*129 + ch];
            mx = fmaxf(mx, v); mn = fminf(mn, v);
        }
        g_Mx[(size_t)blockIdx.x*512 + e] = mx;
        g_Mn[(size_t)blockIdx.x*512 + e] = mn;
    }
    __syncthreads();
    if (t < 128) {
        g_psum[(size_t)t*4096 + blockIdx.x] = ps[t] + ps[128 + t];
        g_psq [(size_t)t*4096 + blockIdx.x] = pq[t] + pq[128 + t];
    }
}

// ------------- finalize BN stats: one block per channel, coalesced float4 reads ------------
__global__ __launch_bounds__(256)
void k_fin(const float* __restrict__ gma, const float* __restrict__ beta,
           int OC, int layer) {
    int c = blockIdx.x, t = threadIdx.x;
    const float4* Ps = (const float4*)(g_psum + (size_t)c * 4096);
    const float4* Pq = (const float4*)(g_psq  + (size_t)c * 4096);
    float s = 0.f, s2 = 0.f;
#pragma unroll
    for (int i = t; i < 1024; i += 256) {
        float4 a = Ps[i];
        float4 b = Pq[i];
        s  += a.x + a.y + a.z + a.w;
        s2 += b.x + b.y + b.z + b.w;
    }
#pragma unroll
    for (int off = 16; off; off >>= 1) {
        s  += __shfl_down_sync(0xffffffffu, s, off);
        s2 += __shfl_down_sync(0xffffffffu, s2, off);
    }
    __shared__ float a[8], a2[8];
    if ((t & 31) == 0) { a[t>>5] = s; a2[t>>5] = s2; }
    __syncthreads();
    if (t == 0) {
        double S = 0.0, S2 = 0.0;
#pragma unroll
        for (int wb = 0; wb < 8; wb++) { S += (double)a[wb]; S2 += (double)a2[wb]; }
        double inv  = 1.0 / (double)NROWS;
        double mean = S * inv;
        double var  = S2 * inv - mean * mean;
        float scale = (float)((double)gma[c] * rsqrt(var + 1e-5));
        float shift = (float)((double)beta[c] - mean * (double)scale);
        g_scale[layer][c] = scale;
        g_shift[layer][c] = shift;
    }
}

// ---------- pool: BN2 applied to raw min/max (monotone-exact) + transposed write -----------
__global__ __launch_bounds__(128)
void k_pool(float* __restrict__ out) {
    __shared__ float sm[128*33];
    int t = threadIdx.x;
    float sc = g_scale[2][t], sh = g_shift[2][t];
    int q0 = blockIdx.x * 32;
    int b  = q0 >> 10;
    const float* src = (sc > 0.f) ? g_Mx : g_Mn;
#pragma unroll 4
    for (int qi = 0; qi < 32; qi++) {
        float v = src[(size_t)(q0 + qi)*128 + t];
        sm[t*33 + qi] = fmaxf(fmaf(v, sc, sh), 0.f);
    }
    __syncthreads();
    int mloc = t & 31, og = t >> 5;
    int mg = q0 & 1023;
#pragma unroll
    for (int i = 0; i < 32; i++) {
        int oc = og + i*4;
        out[49152 + ((size_t)(b*128 + oc))*1024 + mg + mloc] = sm[oc*33 + mloc];
    }
}

// ------------------------- launch --------------------------------------------------------
extern "C" void kernel_launch(void* const* d_in, const int* in_sizes, int n_in,
                              void* d_out, int out_size) {
    const float* xyz = (const float*)d_in[0];
    const float* pts = (const float*)d_in[1];
    const float* w0  = (const float*)d_in[2];
    const float* g0  = (const float*)d_in[4];
    const float* be0 = (const float*)d_in[5];
    const float* w1  = (const float*)d_in[6];
    const float* g1  = (const float*)d_in[8];
    const float* be1 = (const float*)d_in[9];
    const float* w2  = (const float*)d_in[10];
    const float* g2  = (const float*)d_in[12];
    const float* be2 = (const float*)d_in[13];
    float* out = (float*)d_out;

    const int SMEM2 = 8704 * 4;    // 34816 B
    const int SMEM3 = 17152 * 4;   // 68608 B
    cudaFuncSetAttribute(k_gemm2, cudaFuncAttributeMaxDynamicSharedMemorySize, SMEM2);
    cudaFuncSetAttribute(k_gemm3, cudaFuncAttributeMaxDynamicSharedMemorySize, SMEM3);

    k_init0<<<32, 256>>>(w0);
    k_init1<<<32, 256>>>(w1);
    k_init2<<<32, 256>>>(w2);
    k_front<<<208, 1024>>>(xyz, pts, out);   // <- launch #4: profiled
    k_knn<<<B_*NP_, 128>>>();

    k_gemm1<<<NROWS/128, 256>>>(xyz);
    k_fin<<<64, 256>>>(g0, be0, 64, 0);

    k_gemm2<<<NROWS/128, 128, SMEM2>>>();
    k_fin<<<64, 256>>>(g1, be1, 64, 1);

    k_gemm3<<<NROWS/128, 256, SMEM3>>>();
    k_fin<<<128, 256>>>(g2, be2, 128, 2);

    k_pool<<<B_*NP_/32, 128>>>(out);
}